// round 1
// baseline (speedup 1.0000x reference)
#include <cuda_runtime.h>
#include <math.h>

#define Bq 4
#define Tt 1024
#define Cc 768
#define Hh 12
#define Dd 64
#define Ll 12
#define BT 4096

// ---------------- scratch (device globals: no allocation allowed) ------------
__device__ float g_x[BT * Cc];        // residual stream
__device__ float g_h[BT * Cc];        // LN output
__device__ float g_qkv[BT * 3 * Cc];  // qkv projection
__device__ float g_y[BT * Cc];        // attention output
__device__ float g_ff[BT * 4 * Cc];   // MLP hidden

// ---------------- embedding --------------------------------------------------
__global__ void embed_kernel(const int* __restrict__ idx, const float* __restrict__ wte,
                             const float* __restrict__ wpe, float* __restrict__ x) {
    int row = blockIdx.x;              // 0..4095  (b*1024 + t)
    int tok = idx[row];
    int t = row & (Tt - 1);
    int c = threadIdx.x * 4;           // 192 threads * 4 = 768
    float4 a = *(const float4*)(wte + (size_t)tok * Cc + c);
    float4 p = *(const float4*)(wpe + (size_t)t * Cc + c);
    a.x += p.x; a.y += p.y; a.z += p.z; a.w += p.w;
    *(float4*)(x + (size_t)row * Cc + c) = a;
}

// ---------------- layernorm ---------------------------------------------------
__global__ void ln_kernel(const float* __restrict__ in, const float* __restrict__ w,
                          const float* __restrict__ b, float* __restrict__ out) {
    int row = blockIdx.x;
    int t = threadIdx.x;               // 256 threads, 3 elems each
    const float* xr = in + (size_t)row * Cc;
    float v[3];
    float s = 0.f, s2 = 0.f;
#pragma unroll
    for (int i = 0; i < 3; i++) { v[i] = xr[t + i * 256]; s += v[i]; s2 += v[i] * v[i]; }
#pragma unroll
    for (int m = 16; m; m >>= 1) {
        s  += __shfl_xor_sync(0xffffffffu, s, m);
        s2 += __shfl_xor_sync(0xffffffffu, s2, m);
    }
    __shared__ float rs[8], rs2[8];
    if ((t & 31) == 0) { rs[t >> 5] = s; rs2[t >> 5] = s2; }
    __syncthreads();
    s = 0.f; s2 = 0.f;
#pragma unroll
    for (int i = 0; i < 8; i++) { s += rs[i]; s2 += rs2[i]; }
    float mu = s * (1.0f / Cc);
    float var = s2 * (1.0f / Cc) - mu * mu;
    float rstd = rsqrtf(var + 1e-5f);
#pragma unroll
    for (int i = 0; i < 3; i++) {
        int c = t + i * 256;
        out[(size_t)row * Cc + c] = (v[i] - mu) * rstd * w[c] + b[c];
    }
}

// ---------------- GEMM: out = A[M,K] @ W[K,N] + bias (+gelu) (+residual) -----
__device__ __forceinline__ float gelu_f(float x) {
    float x3 = x * x * x;
    return 0.5f * x * (1.f + tanhf(0.7978845608028654f * (x + 0.044715f * x3)));
}

template <bool GELU, bool RES>
__global__ void __launch_bounds__(256) gemm_kernel(
    const float* __restrict__ A, const float* __restrict__ W,
    const float* __restrict__ bias, const float* __restrict__ res,
    float* __restrict__ out, int M, int N, int K) {
    __shared__ float As[8][128];   // transposed A tile
    __shared__ float Ws[8][128];
    int tid = threadIdx.x;
    int tr = tid >> 4, tc = tid & 15;
    int arow = tid >> 1, acol = (tid & 1) * 4;
    int wrow = tid >> 5, wcol = (tid & 31) * 4;
    const float* Aptr = A + (size_t)(blockIdx.y * 128 + arow) * K + acol;
    const float* Wptr = W + (size_t)wrow * N + blockIdx.x * 128 + wcol;

    float acc[8][8];
#pragma unroll
    for (int i = 0; i < 8; i++)
#pragma unroll
        for (int j = 0; j < 8; j++) acc[i][j] = 0.f;

    for (int kt = 0; kt < K; kt += 8) {
        float4 av = *(const float4*)(Aptr + kt);
        float4 wv = *(const float4*)(Wptr + (size_t)kt * N);
        As[acol + 0][arow] = av.x; As[acol + 1][arow] = av.y;
        As[acol + 2][arow] = av.z; As[acol + 3][arow] = av.w;
        *(float4*)&Ws[wrow][wcol] = wv;
        __syncthreads();
#pragma unroll
        for (int k = 0; k < 8; k++) {
            float af[8], wf[8];
            *(float4*)(af)     = *(const float4*)&As[k][tr * 8];
            *(float4*)(af + 4) = *(const float4*)&As[k][tr * 8 + 4];
            *(float4*)(wf)     = *(const float4*)&Ws[k][tc * 8];
            *(float4*)(wf + 4) = *(const float4*)&Ws[k][tc * 8 + 4];
#pragma unroll
            for (int i = 0; i < 8; i++)
#pragma unroll
                for (int j = 0; j < 8; j++) acc[i][j] += af[i] * wf[j];
        }
        __syncthreads();
    }

    int r0 = blockIdx.y * 128 + tr * 8;
    int c0 = blockIdx.x * 128 + tc * 8;
#pragma unroll
    for (int i = 0; i < 8; i++) {
#pragma unroll
        for (int j = 0; j < 8; j++) {
            float val = acc[i][j] + bias[c0 + j];
            if (GELU) val = gelu_f(val);
            if (RES) val += res[(size_t)(r0 + i) * N + c0 + j];
            out[(size_t)(r0 + i) * N + c0 + j] = val;
        }
    }
}

// ---------------- flash attention (fp32, 64x64 tiles) -------------------------
// grid: (T/64, B*H), block 256. smem: Q[64][68], Kt[64][68](d-major), V[64][68], P[64][68]
__global__ void __launch_bounds__(256) attn_kernel(const float* __restrict__ qkv,
                                                   float* __restrict__ y) {
    extern __shared__ float sm[];
    float* sQ = sm;
    float* sK = sm + 64 * 68;      // [d][key]
    float* sV = sm + 2 * 64 * 68;  // [key][d]
    float* sP = sm + 3 * 64 * 68;  // [q][key]

    const int qb = blockIdx.x;
    const int b = blockIdx.y / Hh, h = blockIdx.y % Hh;
    const int tid = threadIdx.x;
    const int ty = tid >> 4, tx = tid & 15;
    const float* base = qkv + (size_t)b * Tt * (3 * Cc) + h * Dd;

    // load Q tile (64 rows x 64 d)
#pragma unroll
    for (int l = 0; l < 4; l++) {
        int id = tid + l * 256;
        int r = id >> 4, c4 = (id & 15) * 4;
        float4 v = *(const float4*)(base + (size_t)(qb * 64 + r) * (3 * Cc) + c4);
        *(float4*)&sQ[r * 68 + c4] = v;
    }

    float o[4][4] = {};
    float mi[4], li[4];
#pragma unroll
    for (int i = 0; i < 4; i++) { mi[i] = -INFINITY; li[i] = 0.f; }

    for (int kb = 0; kb <= qb; kb++) {
        __syncthreads();  // previous iteration done with sK/sV/sP
#pragma unroll
        for (int l = 0; l < 4; l++) {
            int id = tid + l * 256;
            int r = id >> 4, c4 = (id & 15) * 4;
            const float* kvrow = base + (size_t)(kb * 64 + r) * (3 * Cc);
            float4 kv = *(const float4*)(kvrow + Cc + c4);
            sK[(c4 + 0) * 68 + r] = kv.x; sK[(c4 + 1) * 68 + r] = kv.y;
            sK[(c4 + 2) * 68 + r] = kv.z; sK[(c4 + 3) * 68 + r] = kv.w;
            float4 vv = *(const float4*)(kvrow + 2 * Cc + c4);
            *(float4*)&sV[r * 68 + c4] = vv;
        }
        __syncthreads();

        // S = Q K^T (64x64), each thread 4x4
        float s[4][4] = {};
#pragma unroll 8
        for (int d = 0; d < 64; d++) {
            float4 kf = *(const float4*)&sK[d * 68 + tx * 4];
            float q0 = sQ[(ty * 4 + 0) * 68 + d];
            float q1 = sQ[(ty * 4 + 1) * 68 + d];
            float q2 = sQ[(ty * 4 + 2) * 68 + d];
            float q3 = sQ[(ty * 4 + 3) * 68 + d];
            s[0][0] += q0 * kf.x; s[0][1] += q0 * kf.y; s[0][2] += q0 * kf.z; s[0][3] += q0 * kf.w;
            s[1][0] += q1 * kf.x; s[1][1] += q1 * kf.y; s[1][2] += q1 * kf.z; s[1][3] += q1 * kf.w;
            s[2][0] += q2 * kf.x; s[2][1] += q2 * kf.y; s[2][2] += q2 * kf.z; s[2][3] += q2 * kf.w;
            s[3][0] += q3 * kf.x; s[3][1] += q3 * kf.y; s[3][2] += q3 * kf.z; s[3][3] += q3 * kf.w;
        }

        const bool diag = (kb == qb);
#pragma unroll
        for (int i = 0; i < 4; i++) {
            int qi = ty * 4 + i;
#pragma unroll
            for (int j = 0; j < 4; j++) {
                float sv = s[i][j] * 0.125f;   // 1/sqrt(64)
                if (diag && (tx * 4 + j) > qi) sv = -INFINITY;
                s[i][j] = sv;
            }
            float rm = fmaxf(fmaxf(s[i][0], s[i][1]), fmaxf(s[i][2], s[i][3]));
#pragma unroll
            for (int m = 8; m; m >>= 1) rm = fmaxf(rm, __shfl_xor_sync(0xffffffffu, rm, m));
            float mnew = fmaxf(mi[i], rm);
            float alpha = __expf(mi[i] - mnew);
            float rsum = 0.f;
#pragma unroll
            for (int j = 0; j < 4; j++) {
                float p = __expf(s[i][j] - mnew);
                s[i][j] = p;
                rsum += p;
            }
#pragma unroll
            for (int m = 8; m; m >>= 1) rsum += __shfl_xor_sync(0xffffffffu, rsum, m);
            li[i] = li[i] * alpha + rsum;
            mi[i] = mnew;
#pragma unroll
            for (int j = 0; j < 4; j++) o[i][j] *= alpha;
            *(float4*)&sP[(ty * 4 + i) * 68 + tx * 4] =
                make_float4(s[i][0], s[i][1], s[i][2], s[i][3]);
        }
        __syncthreads();

        // O += P @ V
#pragma unroll 8
        for (int c = 0; c < 64; c++) {
            float4 vf = *(const float4*)&sV[c * 68 + tx * 4];
            float p0 = sP[(ty * 4 + 0) * 68 + c];
            float p1 = sP[(ty * 4 + 1) * 68 + c];
            float p2 = sP[(ty * 4 + 2) * 68 + c];
            float p3 = sP[(ty * 4 + 3) * 68 + c];
            o[0][0] += p0 * vf.x; o[0][1] += p0 * vf.y; o[0][2] += p0 * vf.z; o[0][3] += p0 * vf.w;
            o[1][0] += p1 * vf.x; o[1][1] += p1 * vf.y; o[1][2] += p1 * vf.z; o[1][3] += p1 * vf.w;
            o[2][0] += p2 * vf.x; o[2][1] += p2 * vf.y; o[2][2] += p2 * vf.z; o[2][3] += p2 * vf.w;
            o[3][0] += p3 * vf.x; o[3][1] += p3 * vf.y; o[3][2] += p3 * vf.z; o[3][3] += p3 * vf.w;
        }
    }

#pragma unroll
    for (int i = 0; i < 4; i++) {
        float inv = 1.f / li[i];
        int row = b * Tt + qb * 64 + ty * 4 + i;
#pragma unroll
        for (int j = 0; j < 4; j++)
            y[(size_t)row * Cc + h * Dd + tx * 4 + j] = o[i][j] * inv;
    }
}

// ---------------- final LN + head matvec -------------------------------------
__global__ void head_kernel(const float* __restrict__ x, const float* __restrict__ w,
                            const float* __restrict__ b, const float* __restrict__ wh,
                            float* __restrict__ out) {
    int row = blockIdx.x;
    int t = threadIdx.x;
    const float* xr = x + (size_t)row * Cc;
    float v[3];
    float s = 0.f, s2 = 0.f;
#pragma unroll
    for (int i = 0; i < 3; i++) { v[i] = xr[t + i * 256]; s += v[i]; s2 += v[i] * v[i]; }
#pragma unroll
    for (int m = 16; m; m >>= 1) {
        s  += __shfl_xor_sync(0xffffffffu, s, m);
        s2 += __shfl_xor_sync(0xffffffffu, s2, m);
    }
    __shared__ float rs[8], rs2[8], rd[8];
    if ((t & 31) == 0) { rs[t >> 5] = s; rs2[t >> 5] = s2; }
    __syncthreads();
    s = 0.f; s2 = 0.f;
#pragma unroll
    for (int i = 0; i < 8; i++) { s += rs[i]; s2 += rs2[i]; }
    float mu = s * (1.0f / Cc);
    float var = s2 * (1.0f / Cc) - mu * mu;
    float rstd = rsqrtf(var + 1e-5f);
    float dot = 0.f;
#pragma unroll
    for (int i = 0; i < 3; i++) {
        int c = t + i * 256;
        dot += ((v[i] - mu) * rstd * w[c] + b[c]) * wh[c];
    }
#pragma unroll
    for (int m = 16; m; m >>= 1) dot += __shfl_xor_sync(0xffffffffu, dot, m);
    if ((t & 31) == 0) rd[t >> 5] = dot;
    __syncthreads();
    if (t == 0) {
        float d = 0.f;
#pragma unroll
        for (int i = 0; i < 8; i++) d += rd[i];
        out[row] = d;
    }
}

// ---------------- host launch -------------------------------------------------
extern "C" void kernel_launch(void* const* d_in, const int* in_sizes, int n_in,
                              void* d_out, int out_size) {
    (void)in_sizes; (void)n_in; (void)out_size;
    const int*   idx   = (const int*)d_in[0];
    const float* wte   = (const float*)d_in[1];
    const float* wpe   = (const float*)d_in[2];
    const float* ln1w  = (const float*)d_in[3];
    const float* ln1b  = (const float*)d_in[4];
    const float* wqkv  = (const float*)d_in[5];
    const float* bqkv  = (const float*)d_in[6];
    const float* wao   = (const float*)d_in[7];
    const float* bao   = (const float*)d_in[8];
    const float* ln2w  = (const float*)d_in[9];
    const float* ln2b  = (const float*)d_in[10];
    const float* wfc   = (const float*)d_in[11];
    const float* bfc   = (const float*)d_in[12];
    const float* wfp   = (const float*)d_in[13];
    const float* bfp   = (const float*)d_in[14];
    const float* lnfw  = (const float*)d_in[15];
    const float* lnfb  = (const float*)d_in[16];
    const float* whead = (const float*)d_in[17];

    float *x, *h, *qkv, *y, *ff;
    cudaGetSymbolAddress((void**)&x, g_x);
    cudaGetSymbolAddress((void**)&h, g_h);
    cudaGetSymbolAddress((void**)&qkv, g_qkv);
    cudaGetSymbolAddress((void**)&y, g_y);
    cudaGetSymbolAddress((void**)&ff, g_ff);

    const int ATTN_SMEM = 4 * 64 * 68 * 4;  // 69632 B
    cudaFuncSetAttribute((const void*)attn_kernel,
                         cudaFuncAttributeMaxDynamicSharedMemorySize, ATTN_SMEM);

    embed_kernel<<<BT, 192>>>(idx, wte, wpe, x);

    for (int l = 0; l < Ll; l++) {
        ln_kernel<<<BT, 256>>>(x, ln1w + l * Cc, ln1b + l * Cc, h);
        gemm_kernel<false, false><<<dim3(18, 32), 256>>>(
            h, wqkv + (size_t)l * Cc * 3 * Cc, bqkv + l * 3 * Cc, nullptr, qkv,
            BT, 3 * Cc, Cc);
        attn_kernel<<<dim3(Tt / 64, Bq * Hh), 256, ATTN_SMEM>>>(qkv, y);
        gemm_kernel<false, true><<<dim3(6, 32), 256>>>(
            y, wao + (size_t)l * Cc * Cc, bao + l * Cc, x, x, BT, Cc, Cc);
        ln_kernel<<<BT, 256>>>(x, ln2w + l * Cc, ln2b + l * Cc, h);
        gemm_kernel<true, false><<<dim3(24, 32), 256>>>(
            h, wfc + (size_t)l * Cc * 4 * Cc, bfc + l * 4 * Cc, nullptr, ff,
            BT, 4 * Cc, Cc);
        gemm_kernel<false, true><<<dim3(6, 32), 256>>>(
            ff, wfp + (size_t)l * 4 * Cc * Cc, bfp + l * Cc, x, x, BT, Cc, 4 * Cc);
    }

    head_kernel<<<BT, 256>>>(x, lnfw, lnfb, whead, (float*)d_out);
}

// round 3
// speedup vs baseline: 2.0895x; 2.0895x over previous
#include <cuda_runtime.h>
#include <cuda_bf16.h>
#include <math.h>
#include <stdint.h>

#define Bq 4
#define Tt 1024
#define Cc 768
#define Hh 12
#define Dd 64
#define Ll 12
#define BT 4096

typedef __nv_bfloat16 bf16;

// ---------------- scratch (device globals: no allocation allowed) ------------
__device__ __align__(16) float g_x[BT * Cc];        // residual stream (fp32)
__device__ __align__(16) float g_qkv[BT * 3 * Cc];  // qkv projection (fp32)

// hi/lo split activations (GEMM A-operands)
__device__ __align__(16) bf16 g_hh[BT * Cc];        // LN out hi
__device__ __align__(16) bf16 g_hl[BT * Cc];        // LN out lo
__device__ __align__(16) bf16 g_yh[BT * Cc];        // attn out hi
__device__ __align__(16) bf16 g_yl[BT * Cc];
__device__ __align__(16) bf16 g_ffh[BT * 4 * Cc];   // gelu(fc) hi
__device__ __align__(16) bf16 g_ffl[BT * 4 * Cc];

// hi/lo split TRANSPOSED weights ([N][K] layout, bf16)
__device__ __align__(16) bf16 g_wqkvT_h[Ll * 3 * Cc * Cc];
__device__ __align__(16) bf16 g_wqkvT_l[Ll * 3 * Cc * Cc];
__device__ __align__(16) bf16 g_waoT_h[Ll * Cc * Cc];
__device__ __align__(16) bf16 g_waoT_l[Ll * Cc * Cc];
__device__ __align__(16) bf16 g_wfcT_h[Ll * 4 * Cc * Cc];
__device__ __align__(16) bf16 g_wfcT_l[Ll * 4 * Cc * Cc];
__device__ __align__(16) bf16 g_wfpT_h[Ll * Cc * 4 * Cc];
__device__ __align__(16) bf16 g_wfpT_l[Ll * Cc * 4 * Cc];

// ---------------- helpers -----------------------------------------------------
__device__ __forceinline__ uint32_t smem_u32(const void* p) {
    uint32_t a;
    asm("{ .reg .u64 t; cvta.to.shared.u64 t, %1; cvt.u32.u64 %0, t; }"
        : "=r"(a) : "l"(p));
    return a;
}
__device__ __forceinline__ uint32_t lds32(uint32_t a) {
    uint32_t v;
    asm volatile("ld.shared.b32 %0, [%1];" : "=r"(v) : "r"(a));
    return v;
}
__device__ __forceinline__ void cp16(uint32_t dst, const void* src) {
    asm volatile("cp.async.ca.shared.global [%0], [%1], 16;"
                 :: "r"(dst), "l"(src) : "memory");
}
__device__ __forceinline__ void cp_commit() {
    asm volatile("cp.async.commit_group;" ::: "memory");
}
__device__ __forceinline__ void mma_bf16(float* c, const uint32_t* a,
                                         uint32_t b0, uint32_t b1) {
    asm volatile(
        "mma.sync.aligned.m16n8k16.row.col.f32.bf16.bf16.f32 "
        "{%0,%1,%2,%3}, {%4,%5,%6,%7}, {%8,%9}, {%0,%1,%2,%3};"
        : "+f"(c[0]), "+f"(c[1]), "+f"(c[2]), "+f"(c[3])
        : "r"(a[0]), "r"(a[1]), "r"(a[2]), "r"(a[3]), "r"(b0), "r"(b1));
}
__device__ __forceinline__ void split2(float f, bf16& h, bf16& l) {
    h = __float2bfloat16(f);
    l = __float2bfloat16(f - __bfloat162float(h));
}
__device__ __forceinline__ float gelu_f(float x) {
    float x3 = x * x * x;
    return 0.5f * x * (1.f + tanhf(0.7978845608028654f * (x + 0.044715f * x3)));
}

// ---------------- weight transpose + hi/lo split -------------------------------
// W[K][N] fp32 -> Th[N][K], Tl[N][K] bf16.  grid (N/32, K/32), 256 threads.
__global__ void wsplit_kernel(const float* __restrict__ W, bf16* __restrict__ Th,
                              bf16* __restrict__ Tl, int K, int N) {
    __shared__ float t[32][33];
    int n0 = blockIdx.x * 32, k0 = blockIdx.y * 32;
    int tx = threadIdx.x & 31, ty = threadIdx.x >> 5;  // ty 0..7
#pragma unroll
    for (int j = 0; j < 4; j++)
        t[ty + 8 * j][tx] = W[(size_t)(k0 + ty + 8 * j) * N + n0 + tx];
    __syncthreads();
#pragma unroll
    for (int j = 0; j < 4; j++) {
        int nr = ty + 8 * j;
        float f = t[tx][nr];
        bf16 h, l;
        split2(f, h, l);
        size_t o = (size_t)(n0 + nr) * K + k0 + tx;
        Th[o] = h;
        Tl[o] = l;
    }
}

// ---------------- embedding --------------------------------------------------
__global__ void embed_kernel(const int* __restrict__ idx, const float* __restrict__ wte,
                             const float* __restrict__ wpe, float* __restrict__ x) {
    int row = blockIdx.x;
    int tok = idx[row];
    int t = row & (Tt - 1);
    int c = threadIdx.x * 4;
    float4 a = *(const float4*)(wte + (size_t)tok * Cc + c);
    float4 p = *(const float4*)(wpe + (size_t)t * Cc + c);
    a.x += p.x; a.y += p.y; a.z += p.z; a.w += p.w;
    *(float4*)(x + (size_t)row * Cc + c) = a;
}

// ---------------- layernorm (fp32 in, hi/lo bf16 out) -------------------------
__global__ void ln_kernel(const float* __restrict__ in, const float* __restrict__ w,
                          const float* __restrict__ b, bf16* __restrict__ oh,
                          bf16* __restrict__ ol) {
    int row = blockIdx.x;
    int t = threadIdx.x;
    const float* xr = in + (size_t)row * Cc;
    float v[3];
    float s = 0.f, s2 = 0.f;
#pragma unroll
    for (int i = 0; i < 3; i++) { v[i] = xr[t + i * 256]; s += v[i]; s2 += v[i] * v[i]; }
#pragma unroll
    for (int m = 16; m; m >>= 1) {
        s  += __shfl_xor_sync(0xffffffffu, s, m);
        s2 += __shfl_xor_sync(0xffffffffu, s2, m);
    }
    __shared__ float rs[8], rs2[8];
    if ((t & 31) == 0) { rs[t >> 5] = s; rs2[t >> 5] = s2; }
    __syncthreads();
    s = 0.f; s2 = 0.f;
#pragma unroll
    for (int i = 0; i < 8; i++) { s += rs[i]; s2 += rs2[i]; }
    float mu = s * (1.0f / Cc);
    float var = s2 * (1.0f / Cc) - mu * mu;
    float rstd = rsqrtf(var + 1e-5f);
#pragma unroll
    for (int i = 0; i < 3; i++) {
        int c = t + i * 256;
        float o = (v[i] - mu) * rstd * w[c] + b[c];
        bf16 h, l;
        split2(o, h, l);
        oh[(size_t)row * Cc + c] = h;
        ol[(size_t)row * Cc + c] = l;
    }
}

// ---------------- GEMM via mma.sync bf16 split-3 -------------------------------
// C = A @ B^T(+bias)(+gelu)(+res), A=[M][K] hi/lo bf16, B stored [N][K] hi/lo bf16
// CTA tile 128x128, K-tile 32.  8 warps: warp_m = wid&3 (32 rows), warp_n = wid>>2 (64 cols).
#define SAW 20  // smem row stride in 4B words (16 data words + 4 pad) -> conflict-free
#define OFF_AH 0u
#define OFF_AL 10240u
#define OFF_BH 20480u
#define OFF_BL 30720u
#define BUFSZ 40960u
#define GSM2 (2 * 40960)

template <bool GELU, bool RES, bool SPLIT>
__global__ void __launch_bounds__(256) gemm_mma(
    const bf16* __restrict__ Ah, const bf16* __restrict__ Al,
    const bf16* __restrict__ Bh, const bf16* __restrict__ Bl,
    const float* __restrict__ bias, const float* __restrict__ res,
    float* __restrict__ outf, bf16* __restrict__ outh, bf16* __restrict__ outl,
    int M, int N, int K) {
    extern __shared__ char smem[];
    const uint32_t sb = smem_u32(smem);
    const int tid = threadIdx.x;
    const int lane = tid & 31, wid = tid >> 5;
    const int g = lane >> 2, c = lane & 3;
    const int wm = wid & 3, wn = wid >> 2;
    const int m0 = blockIdx.y * 128, n0 = blockIdx.x * 128;

    const int r_ld = tid >> 2;        // 0..63
    const int q_ld = tid & 3;         // 0..3 (16B chunk within 64B row)
    const uint32_t d0 = (uint32_t)(r_ld * SAW + q_ld * 4) * 4;
    const uint32_t d1 = (uint32_t)((r_ld + 64) * SAW + q_ld * 4) * 4;

    float acc[2][8][4];
#pragma unroll
    for (int mt = 0; mt < 2; mt++)
#pragma unroll
        for (int nt = 0; nt < 8; nt++)
#pragma unroll
            for (int r = 0; r < 4; r++) acc[mt][nt][r] = 0.f;

    const int nkt = K >> 5;

    // stage issue: copy A(hi/lo) rows m0+r, B(hi/lo) rows n0+r, k-slice kt*32
#define ISSUE(KT, BUF)                                                          \
    do {                                                                        \
        uint32_t bs = sb + (BUF) * BUFSZ;                                       \
        size_t ka = (size_t)(m0 + r_ld) * K + (KT) * 32 + q_ld * 8;             \
        size_t kb = (size_t)(n0 + r_ld) * K + (KT) * 32 + q_ld * 8;             \
        cp16(bs + OFF_AH + d0, Ah + ka);                                        \
        cp16(bs + OFF_AH + d1, Ah + ka + (size_t)64 * K);                       \
        cp16(bs + OFF_AL + d0, Al + ka);                                        \
        cp16(bs + OFF_AL + d1, Al + ka + (size_t)64 * K);                       \
        cp16(bs + OFF_BH + d0, Bh + kb);                                        \
        cp16(bs + OFF_BH + d1, Bh + kb + (size_t)64 * K);                       \
        cp16(bs + OFF_BL + d0, Bl + kb);                                        \
        cp16(bs + OFF_BL + d1, Bl + kb + (size_t)64 * K);                       \
        cp_commit();                                                            \
    } while (0)

    ISSUE(0, 0);

    for (int kt = 0; kt < nkt; kt++) {
        int buf = kt & 1;
        if (kt + 1 < nkt) {
            ISSUE(kt + 1, buf ^ 1);
            asm volatile("cp.async.wait_group 1;" ::: "memory");
        } else {
            asm volatile("cp.async.wait_group 0;" ::: "memory");
        }
        __syncthreads();

        uint32_t bs = sb + buf * BUFSZ;
#pragma unroll
        for (int ks = 0; ks < 2; ks++) {
            uint32_t ah[2][4], al[2][4];
            uint32_t abase = bs + OFF_AH +
                             (uint32_t)((wm * 32 + g) * SAW + ks * 8 + c) * 4;
#pragma unroll
            for (int mt = 0; mt < 2; mt++) {
                uint32_t ab = abase + mt * 16 * SAW * 4;
                ah[mt][0] = lds32(ab);
                ah[mt][1] = lds32(ab + 8 * SAW * 4);
                ah[mt][2] = lds32(ab + 16);
                ah[mt][3] = lds32(ab + 8 * SAW * 4 + 16);
                uint32_t ab2 = ab + (OFF_AL - OFF_AH);
                al[mt][0] = lds32(ab2);
                al[mt][1] = lds32(ab2 + 8 * SAW * 4);
                al[mt][2] = lds32(ab2 + 16);
                al[mt][3] = lds32(ab2 + 8 * SAW * 4 + 16);
            }
            uint32_t bbase = bs + OFF_BH +
                             (uint32_t)((wn * 64 + g) * SAW + ks * 8 + c) * 4;
#pragma unroll
            for (int nt = 0; nt < 8; nt++) {
                uint32_t bb = bbase + nt * 8 * SAW * 4;
                uint32_t bh0 = lds32(bb), bh1 = lds32(bb + 16);
                uint32_t bl0 = lds32(bb + (OFF_BL - OFF_BH));
                uint32_t bl1 = lds32(bb + (OFF_BL - OFF_BH) + 16);
#pragma unroll
                for (int mt = 0; mt < 2; mt++) {
                    mma_bf16(acc[mt][nt], ah[mt], bh0, bh1);
                    mma_bf16(acc[mt][nt], al[mt], bh0, bh1);
                    mma_bf16(acc[mt][nt], ah[mt], bl0, bl1);
                }
            }
        }
        __syncthreads();
    }

    // epilogue
#pragma unroll
    for (int mt = 0; mt < 2; mt++) {
        int rbase = m0 + wm * 32 + mt * 16 + g;
#pragma unroll
        for (int nt = 0; nt < 8; nt++) {
            int col = n0 + wn * 64 + nt * 8 + 2 * c;
            float b0v = bias[col], b1v = bias[col + 1];
#pragma unroll
            for (int rr = 0; rr < 2; rr++) {
                int r = rbase + rr * 8;
                float v0 = acc[mt][nt][rr * 2 + 0] + b0v;
                float v1 = acc[mt][nt][rr * 2 + 1] + b1v;
                if (GELU) { v0 = gelu_f(v0); v1 = gelu_f(v1); }
                if (RES) {
                    float2 rv = *(const float2*)(res + (size_t)r * N + col);
                    v0 += rv.x;
                    v1 += rv.y;
                }
                if (SPLIT) {
                    bf16 h0, l0, h1, l1;
                    split2(v0, h0, l0);
                    split2(v1, h1, l1);
                    __nv_bfloat162 hv, lv;
                    hv.x = h0; hv.y = h1;
                    lv.x = l0; lv.y = l1;
                    *(__nv_bfloat162*)(outh + (size_t)r * N + col) = hv;
                    *(__nv_bfloat162*)(outl + (size_t)r * N + col) = lv;
                } else {
                    float2 ov;
                    ov.x = v0;
                    ov.y = v1;
                    *(float2*)(outf + (size_t)r * N + col) = ov;
                }
            }
        }
    }
}

// ---------------- flash attention (fp32, 64x64 tiles; split bf16 output) ------
__global__ void __launch_bounds__(256) attn_kernel(const float* __restrict__ qkv,
                                                   bf16* __restrict__ yh,
                                                   bf16* __restrict__ yl) {
    extern __shared__ float sm[];
    float* sQ = sm;
    float* sK = sm + 64 * 68;
    float* sV = sm + 2 * 64 * 68;
    float* sP = sm + 3 * 64 * 68;

    const int qb = blockIdx.x;
    const int b = blockIdx.y / Hh, h = blockIdx.y % Hh;
    const int tid = threadIdx.x;
    const int ty = tid >> 4, tx = tid & 15;
    const float* base = qkv + (size_t)b * Tt * (3 * Cc) + h * Dd;

#pragma unroll
    for (int l = 0; l < 4; l++) {
        int id = tid + l * 256;
        int r = id >> 4, c4 = (id & 15) * 4;
        float4 v = *(const float4*)(base + (size_t)(qb * 64 + r) * (3 * Cc) + c4);
        *(float4*)&sQ[r * 68 + c4] = v;
    }

    float o[4][4] = {};
    float mi[4], li[4];
#pragma unroll
    for (int i = 0; i < 4; i++) { mi[i] = -INFINITY; li[i] = 0.f; }

    for (int kb = 0; kb <= qb; kb++) {
        __syncthreads();
#pragma unroll
        for (int l = 0; l < 4; l++) {
            int id = tid + l * 256;
            int r = id >> 4, c4 = (id & 15) * 4;
            const float* kvrow = base + (size_t)(kb * 64 + r) * (3 * Cc);
            float4 kv = *(const float4*)(kvrow + Cc + c4);
            sK[(c4 + 0) * 68 + r] = kv.x; sK[(c4 + 1) * 68 + r] = kv.y;
            sK[(c4 + 2) * 68 + r] = kv.z; sK[(c4 + 3) * 68 + r] = kv.w;
            float4 vv = *(const float4*)(kvrow + 2 * Cc + c4);
            *(float4*)&sV[r * 68 + c4] = vv;
        }
        __syncthreads();

        float s[4][4] = {};
#pragma unroll 8
        for (int d = 0; d < 64; d++) {
            float4 kf = *(const float4*)&sK[d * 68 + tx * 4];
            float q0 = sQ[(ty * 4 + 0) * 68 + d];
            float q1 = sQ[(ty * 4 + 1) * 68 + d];
            float q2 = sQ[(ty * 4 + 2) * 68 + d];
            float q3 = sQ[(ty * 4 + 3) * 68 + d];
            s[0][0] += q0 * kf.x; s[0][1] += q0 * kf.y; s[0][2] += q0 * kf.z; s[0][3] += q0 * kf.w;
            s[1][0] += q1 * kf.x; s[1][1] += q1 * kf.y; s[1][2] += q1 * kf.z; s[1][3] += q1 * kf.w;
            s[2][0] += q2 * kf.x; s[2][1] += q2 * kf.y; s[2][2] += q2 * kf.z; s[2][3] += q2 * kf.w;
            s[3][0] += q3 * kf.x; s[3][1] += q3 * kf.y; s[3][2] += q3 * kf.z; s[3][3] += q3 * kf.w;
        }

        const bool diag = (kb == qb);
#pragma unroll
        for (int i = 0; i < 4; i++) {
            int qi = ty * 4 + i;
#pragma unroll
            for (int j = 0; j < 4; j++) {
                float sv = s[i][j] * 0.125f;
                if (diag && (tx * 4 + j) > qi) sv = -INFINITY;
                s[i][j] = sv;
            }
            float rm = fmaxf(fmaxf(s[i][0], s[i][1]), fmaxf(s[i][2], s[i][3]));
#pragma unroll
            for (int m = 8; m; m >>= 1) rm = fmaxf(rm, __shfl_xor_sync(0xffffffffu, rm, m));
            float mnew = fmaxf(mi[i], rm);
            float alpha = __expf(mi[i] - mnew);
            float rsum = 0.f;
#pragma unroll
            for (int j = 0; j < 4; j++) {
                float p = __expf(s[i][j] - mnew);
                s[i][j] = p;
                rsum += p;
            }
#pragma unroll
            for (int m = 8; m; m >>= 1) rsum += __shfl_xor_sync(0xffffffffu, rsum, m);
            li[i] = li[i] * alpha + rsum;
            mi[i] = mnew;
#pragma unroll
            for (int j = 0; j < 4; j++) o[i][j] *= alpha;
            *(float4*)&sP[(ty * 4 + i) * 68 + tx * 4] =
                make_float4(s[i][0], s[i][1], s[i][2], s[i][3]);
        }
        __syncthreads();

#pragma unroll 8
        for (int c = 0; c < 64; c++) {
            float4 vf = *(const float4*)&sV[c * 68 + tx * 4];
            float p0 = sP[(ty * 4 + 0) * 68 + c];
            float p1 = sP[(ty * 4 + 1) * 68 + c];
            float p2 = sP[(ty * 4 + 2) * 68 + c];
            float p3 = sP[(ty * 4 + 3) * 68 + c];
            o[0][0] += p0 * vf.x; o[0][1] += p0 * vf.y; o[0][2] += p0 * vf.z; o[0][3] += p0 * vf.w;
            o[1][0] += p1 * vf.x; o[1][1] += p1 * vf.y; o[1][2] += p1 * vf.z; o[1][3] += p1 * vf.w;
            o[2][0] += p2 * vf.x; o[2][1] += p2 * vf.y; o[2][2] += p2 * vf.z; o[2][3] += p2 * vf.w;
            o[3][0] += p3 * vf.x; o[3][1] += p3 * vf.y; o[3][2] += p3 * vf.z; o[3][3] += p3 * vf.w;
        }
    }

#pragma unroll
    for (int i = 0; i < 4; i++) {
        float inv = 1.f / li[i];
        int row = b * Tt + qb * 64 + ty * 4 + i;
        size_t ob = (size_t)row * Cc + h * Dd + tx * 4;
        bf16 h0, l0, h1, l1, h2, l2, h3, l3;
        split2(o[i][0] * inv, h0, l0);
        split2(o[i][1] * inv, h1, l1);
        split2(o[i][2] * inv, h2, l2);
        split2(o[i][3] * inv, h3, l3);
        __nv_bfloat162 a, bb2, aL, bL;
        a.x = h0; a.y = h1; bb2.x = h2; bb2.y = h3;
        aL.x = l0; aL.y = l1; bL.x = l2; bL.y = l3;
        *(__nv_bfloat162*)(yh + ob) = a;
        *(__nv_bfloat162*)(yh + ob + 2) = bb2;
        *(__nv_bfloat162*)(yl + ob) = aL;
        *(__nv_bfloat162*)(yl + ob + 2) = bL;
    }
}

// ---------------- final LN + head matvec -------------------------------------
__global__ void head_kernel(const float* __restrict__ x, const float* __restrict__ w,
                            const float* __restrict__ b, const float* __restrict__ wh,
                            float* __restrict__ out) {
    int row = blockIdx.x;
    int t = threadIdx.x;
    const float* xr = x + (size_t)row * Cc;
    float v[3];
    float s = 0.f, s2 = 0.f;
#pragma unroll
    for (int i = 0; i < 3; i++) { v[i] = xr[t + i * 256]; s += v[i]; s2 += v[i] * v[i]; }
#pragma unroll
    for (int m = 16; m; m >>= 1) {
        s  += __shfl_xor_sync(0xffffffffu, s, m);
        s2 += __shfl_xor_sync(0xffffffffu, s2, m);
    }
    __shared__ float rs[8], rs2[8], rd[8];
    if ((t & 31) == 0) { rs[t >> 5] = s; rs2[t >> 5] = s2; }
    __syncthreads();
    s = 0.f; s2 = 0.f;
#pragma unroll
    for (int i = 0; i < 8; i++) { s += rs[i]; s2 += rs2[i]; }
    float mu = s * (1.0f / Cc);
    float var = s2 * (1.0f / Cc) - mu * mu;
    float rstd = rsqrtf(var + 1e-5f);
    float dot = 0.f;
#pragma unroll
    for (int i = 0; i < 3; i++) {
        int c = t + i * 256;
        dot += ((v[i] - mu) * rstd * w[c] + b[c]) * wh[c];
    }
#pragma unroll
    for (int m = 16; m; m >>= 1) dot += __shfl_xor_sync(0xffffffffu, dot, m);
    if ((t & 31) == 0) rd[t >> 5] = dot;
    __syncthreads();
    if (t == 0) {
        float d = 0.f;
#pragma unroll
        for (int i = 0; i < 8; i++) d += rd[i];
        out[row] = d;
    }
}

// ---------------- host launch -------------------------------------------------
extern "C" void kernel_launch(void* const* d_in, const int* in_sizes, int n_in,
                              void* d_out, int out_size) {
    (void)in_sizes; (void)n_in; (void)out_size;
    const int*   idx   = (const int*)d_in[0];
    const float* wte   = (const float*)d_in[1];
    const float* wpe   = (const float*)d_in[2];
    const float* ln1w  = (const float*)d_in[3];
    const float* ln1b  = (const float*)d_in[4];
    const float* wqkv  = (const float*)d_in[5];
    const float* bqkv  = (const float*)d_in[6];
    const float* wao   = (const float*)d_in[7];
    const float* bao   = (const float*)d_in[8];
    const float* ln2w  = (const float*)d_in[9];
    const float* ln2b  = (const float*)d_in[10];
    const float* wfc   = (const float*)d_in[11];
    const float* bfc   = (const float*)d_in[12];
    const float* wfp   = (const float*)d_in[13];
    const float* bfp   = (const float*)d_in[14];
    const float* lnfw  = (const float*)d_in[15];
    const float* lnfb  = (const float*)d_in[16];
    const float* whead = (const float*)d_in[17];

    float *x, *qkv;
    bf16 *hh, *hl, *yh, *yl, *ffh, *ffl;
    bf16 *wqkvTh, *wqkvTl, *waoTh, *waoTl, *wfcTh, *wfcTl, *wfpTh, *wfpTl;
    cudaGetSymbolAddress((void**)&x, g_x);
    cudaGetSymbolAddress((void**)&qkv, g_qkv);
    cudaGetSymbolAddress((void**)&hh, g_hh);
    cudaGetSymbolAddress((void**)&hl, g_hl);
    cudaGetSymbolAddress((void**)&yh, g_yh);
    cudaGetSymbolAddress((void**)&yl, g_yl);
    cudaGetSymbolAddress((void**)&ffh, g_ffh);
    cudaGetSymbolAddress((void**)&ffl, g_ffl);
    cudaGetSymbolAddress((void**)&wqkvTh, g_wqkvT_h);
    cudaGetSymbolAddress((void**)&wqkvTl, g_wqkvT_l);
    cudaGetSymbolAddress((void**)&waoTh, g_waoT_h);
    cudaGetSymbolAddress((void**)&waoTl, g_waoT_l);
    cudaGetSymbolAddress((void**)&wfcTh, g_wfcT_h);
    cudaGetSymbolAddress((void**)&wfcTl, g_wfcT_l);
    cudaGetSymbolAddress((void**)&wfpTh, g_wfpT_h);
    cudaGetSymbolAddress((void**)&wfpTl, g_wfpT_l);

    const int ATTN_SMEM = 4 * 64 * 68 * 4;
    cudaFuncSetAttribute((const void*)attn_kernel,
                         cudaFuncAttributeMaxDynamicSharedMemorySize, ATTN_SMEM);
    cudaFuncSetAttribute((const void*)gemm_mma<false, false, false>,
                         cudaFuncAttributeMaxDynamicSharedMemorySize, GSM2);
    cudaFuncSetAttribute((const void*)gemm_mma<false, true, false>,
                         cudaFuncAttributeMaxDynamicSharedMemorySize, GSM2);
    cudaFuncSetAttribute((const void*)gemm_mma<true, false, true>,
                         cudaFuncAttributeMaxDynamicSharedMemorySize, GSM2);

    // weight transpose + split (every launch; deterministic)
    for (int l = 0; l < Ll; l++) {
        wsplit_kernel<<<dim3(3 * Cc / 32, Cc / 32), 256>>>(
            wqkv + (size_t)l * Cc * 3 * Cc, wqkvTh + (size_t)l * 3 * Cc * Cc,
            wqkvTl + (size_t)l * 3 * Cc * Cc, Cc, 3 * Cc);
        wsplit_kernel<<<dim3(Cc / 32, Cc / 32), 256>>>(
            wao + (size_t)l * Cc * Cc, waoTh + (size_t)l * Cc * Cc,
            waoTl + (size_t)l * Cc * Cc, Cc, Cc);
        wsplit_kernel<<<dim3(4 * Cc / 32, Cc / 32), 256>>>(
            wfc + (size_t)l * Cc * 4 * Cc, wfcTh + (size_t)l * 4 * Cc * Cc,
            wfcTl + (size_t)l * 4 * Cc * Cc, Cc, 4 * Cc);
        wsplit_kernel<<<dim3(Cc / 32, 4 * Cc / 32), 256>>>(
            wfp + (size_t)l * 4 * Cc * Cc, wfpTh + (size_t)l * Cc * 4 * Cc,
            wfpTl + (size_t)l * Cc * 4 * Cc, 4 * Cc, Cc);
    }

    embed_kernel<<<BT, 192>>>(idx, wte, wpe, x);

    for (int l = 0; l < Ll; l++) {
        ln_kernel<<<BT, 256>>>(x, ln1w + l * Cc, ln1b + l * Cc, hh, hl);
        gemm_mma<false, false, false><<<dim3(18, 32), 256, GSM2>>>(
            hh, hl, wqkvTh + (size_t)l * 3 * Cc * Cc, wqkvTl + (size_t)l * 3 * Cc * Cc,
            bqkv + l * 3 * Cc, nullptr, qkv, nullptr, nullptr, BT, 3 * Cc, Cc);
        attn_kernel<<<dim3(Tt / 64, Bq * Hh), 256, ATTN_SMEM>>>(qkv, yh, yl);
        gemm_mma<false, true, false><<<dim3(6, 32), 256, GSM2>>>(
            yh, yl, waoTh + (size_t)l * Cc * Cc, waoTl + (size_t)l * Cc * Cc,
            bao + l * Cc, x, x, nullptr, nullptr, BT, Cc, Cc);
        ln_kernel<<<BT, 256>>>(x, ln2w + l * Cc, ln2b + l * Cc, hh, hl);
        gemm_mma<true, false, true><<<dim3(24, 32), 256, GSM2>>>(
            hh, hl, wfcTh + (size_t)l * 4 * Cc * Cc, wfcTl + (size_t)l * 4 * Cc * Cc,
            bfc + l * 4 * Cc, nullptr, nullptr, ffh, ffl, BT, 4 * Cc, Cc);
        gemm_mma<false, true, false><<<dim3(6, 32), 256, GSM2>>>(
            ffh, ffl, wfpTh + (size_t)l * Cc * 4 * Cc, wfpTl + (size_t)l * Cc * 4 * Cc,
            bfp + l * Cc, x, x, nullptr, nullptr, BT, Cc, 4 * Cc);
    }

    head_kernel<<<BT, 256>>>(x, lnfw, lnfb, whead, (float*)d_out);
}

// round 4
// speedup vs baseline: 3.2575x; 1.5590x over previous
#include <cuda_runtime.h>
#include <cuda_fp16.h>
#include <math.h>
#include <stdint.h>

#define Bq 4
#define Tt 1024
#define Cc 768
#define Hh 12
#define Dd 64
#define Ll 12
#define BT 4096

typedef __half f16;

// ---------------- scratch (device globals) ------------------------------------
__device__ __align__(16) float g_x[BT * Cc];          // residual stream (fp32)
__device__ __align__(16) f16 g_qkv16[BT * 3 * Cc];    // qkv (fp16)

__device__ __align__(16) f16 g_hh[BT * Cc];           // LN out hi
__device__ __align__(16) f16 g_hl[BT * Cc];           // LN out lo
__device__ __align__(16) f16 g_yh[BT * Cc];           // attn out hi
__device__ __align__(16) f16 g_yl[BT * Cc];
__device__ __align__(16) f16 g_ffh[BT * 4 * Cc];      // gelu(fc) hi
__device__ __align__(16) f16 g_ffl[BT * 4 * Cc];

// transposed fp16 weights [N][K]
__device__ __align__(16) f16 g_wqkvT[Ll * 3 * Cc * Cc];
__device__ __align__(16) f16 g_waoT[Ll * Cc * Cc];
__device__ __align__(16) f16 g_wfcT[Ll * 4 * Cc * Cc];
__device__ __align__(16) f16 g_wfpT[Ll * Cc * 4 * Cc];

// ---------------- helpers -----------------------------------------------------
__device__ __forceinline__ uint32_t smem_u32(const void* p) {
    uint32_t a;
    asm("{ .reg .u64 t; cvta.to.shared.u64 t, %1; cvt.u32.u64 %0, t; }"
        : "=r"(a) : "l"(p));
    return a;
}
__device__ __forceinline__ uint32_t lds32(uint32_t a) {
    uint32_t v;
    asm volatile("ld.shared.b32 %0, [%1];" : "=r"(v) : "r"(a));
    return v;
}
__device__ __forceinline__ void cp16(uint32_t dst, const void* src) {
    asm volatile("cp.async.ca.shared.global [%0], [%1], 16;"
                 :: "r"(dst), "l"(src) : "memory");
}
__device__ __forceinline__ void cp_commit() {
    asm volatile("cp.async.commit_group;" ::: "memory");
}
__device__ __forceinline__ void mma16(float* c, const uint32_t* a,
                                      uint32_t b0, uint32_t b1) {
    asm volatile(
        "mma.sync.aligned.m16n8k16.row.col.f32.f16.f16.f32 "
        "{%0,%1,%2,%3}, {%4,%5,%6,%7}, {%8,%9}, {%0,%1,%2,%3};"
        : "+f"(c[0]), "+f"(c[1]), "+f"(c[2]), "+f"(c[3])
        : "r"(a[0]), "r"(a[1]), "r"(a[2]), "r"(a[3]), "r"(b0), "r"(b1));
}
__device__ __forceinline__ void split2(float f, f16& h, f16& l) {
    h = __float2half_rn(f);
    l = __float2half_rn(f - __half2float(h));
}
__device__ __forceinline__ float gelu_f(float x) {
    float x3 = x * x * x;
    return 0.5f * x * (1.f + tanhf(0.7978845608028654f * (x + 0.044715f * x3)));
}
__device__ __forceinline__ uint32_t packh2(float a, float b) {
    __half2 h = __floats2half2_rn(a, b);
    return *(uint32_t*)&h;
}

// ---------------- weight transpose to fp16 ------------------------------------
// W[K][N] fp32 -> WT[N][K] fp16.  grid (N/32, K/32), 256 threads.
__global__ void wsplit_kernel(const float* __restrict__ W, f16* __restrict__ Th,
                              int K, int N) {
    __shared__ float t[32][33];
    int n0 = blockIdx.x * 32, k0 = blockIdx.y * 32;
    int tx = threadIdx.x & 31, ty = threadIdx.x >> 5;
#pragma unroll
    for (int j = 0; j < 4; j++)
        t[ty + 8 * j][tx] = W[(size_t)(k0 + ty + 8 * j) * N + n0 + tx];
    __syncthreads();
#pragma unroll
    for (int j = 0; j < 4; j++) {
        int nr = ty + 8 * j;
        Th[(size_t)(n0 + nr) * K + k0 + tx] = __float2half_rn(t[tx][nr]);
    }
}

// ---------------- embedding ---------------------------------------------------
__global__ void embed_kernel(const int* __restrict__ idx, const float* __restrict__ wte,
                             const float* __restrict__ wpe, float* __restrict__ x) {
    int row = blockIdx.x;
    int tok = idx[row];
    int t = row & (Tt - 1);
    int c = threadIdx.x * 4;
    float4 a = *(const float4*)(wte + (size_t)tok * Cc + c);
    float4 p = *(const float4*)(wpe + (size_t)t * Cc + c);
    a.x += p.x; a.y += p.y; a.z += p.z; a.w += p.w;
    *(float4*)(x + (size_t)row * Cc + c) = a;
}

// ---------------- layernorm (fp32 in, hi/lo fp16 out) -------------------------
__global__ void ln_kernel(const float* __restrict__ in, const float* __restrict__ w,
                          const float* __restrict__ b, f16* __restrict__ oh,
                          f16* __restrict__ ol) {
    int row = blockIdx.x;
    int t = threadIdx.x;
    const float* xr = in + (size_t)row * Cc;
    float v[3];
    float s = 0.f, s2 = 0.f;
#pragma unroll
    for (int i = 0; i < 3; i++) { v[i] = xr[t + i * 256]; s += v[i]; s2 += v[i] * v[i]; }
#pragma unroll
    for (int m = 16; m; m >>= 1) {
        s  += __shfl_xor_sync(0xffffffffu, s, m);
        s2 += __shfl_xor_sync(0xffffffffu, s2, m);
    }
    __shared__ float rs[8], rs2[8];
    if ((t & 31) == 0) { rs[t >> 5] = s; rs2[t >> 5] = s2; }
    __syncthreads();
    s = 0.f; s2 = 0.f;
#pragma unroll
    for (int i = 0; i < 8; i++) { s += rs[i]; s2 += rs2[i]; }
    float mu = s * (1.0f / Cc);
    float var = s2 * (1.0f / Cc) - mu * mu;
    float rstd = rsqrtf(var + 1e-5f);
#pragma unroll
    for (int i = 0; i < 3; i++) {
        int c = t + i * 256;
        float o = (v[i] - mu) * rstd * w[c] + b[c];
        f16 h, l;
        split2(o, h, l);
        oh[(size_t)row * Cc + c] = h;
        ol[(size_t)row * Cc + c] = l;
    }
}

// ---------------- GEMM via mma.sync fp16 split-2 -------------------------------
// C = A @ B^T(+bias)(+gelu)(+res).  A = Ah+Al fp16 [M][K]; B fp16 [N][K].
// CTA 128x128, ktile 32, 8 warps (wm = wid&3 -> 32 rows, wn = wid>>2 -> 64 cols).
#define SAW 20
#define OFF_AH 0u
#define OFF_AL 10240u
#define OFF_B  20480u
#define BUFSZ  30720u
#define GSM2   (2 * 30720)

// OUTM: 0 = fp32 out (+res opt), 1 = fp16 single out, 2 = fp16 hi/lo out
template <bool GELU, bool RES, int OUTM>
__global__ void __launch_bounds__(256) gemm_mma(
    const f16* __restrict__ Ah, const f16* __restrict__ Al,
    const f16* __restrict__ B,
    const float* __restrict__ bias, const float* __restrict__ res,
    float* __restrict__ outf, f16* __restrict__ outh, f16* __restrict__ outl,
    int M, int N, int K) {
    extern __shared__ char smem[];
    const uint32_t sb = smem_u32(smem);
    const int tid = threadIdx.x;
    const int lane = tid & 31, wid = tid >> 5;
    const int g = lane >> 2, c = lane & 3;
    const int wm = wid & 3, wn = wid >> 2;
    const int m0 = blockIdx.y * 128, n0 = blockIdx.x * 128;

    const int r_ld = tid >> 2;
    const int q_ld = tid & 3;
    const uint32_t d0 = (uint32_t)(r_ld * SAW + q_ld * 4) * 4;
    const uint32_t d1 = (uint32_t)((r_ld + 64) * SAW + q_ld * 4) * 4;

    float acc[2][8][4];
#pragma unroll
    for (int mt = 0; mt < 2; mt++)
#pragma unroll
        for (int nt = 0; nt < 8; nt++)
#pragma unroll
            for (int r = 0; r < 4; r++) acc[mt][nt][r] = 0.f;

    const int nkt = K >> 5;

#define ISSUE(KT, BUF)                                                          \
    do {                                                                        \
        uint32_t bs = sb + (BUF) * BUFSZ;                                       \
        size_t ka = (size_t)(m0 + r_ld) * K + (KT) * 32 + q_ld * 8;             \
        size_t kb = (size_t)(n0 + r_ld) * K + (KT) * 32 + q_ld * 8;             \
        cp16(bs + OFF_AH + d0, Ah + ka);                                        \
        cp16(bs + OFF_AH + d1, Ah + ka + (size_t)64 * K);                       \
        cp16(bs + OFF_AL + d0, Al + ka);                                        \
        cp16(bs + OFF_AL + d1, Al + ka + (size_t)64 * K);                       \
        cp16(bs + OFF_B + d0, B + kb);                                          \
        cp16(bs + OFF_B + d1, B + kb + (size_t)64 * K);                         \
        cp_commit();                                                            \
    } while (0)

    ISSUE(0, 0);

    for (int kt = 0; kt < nkt; kt++) {
        int buf = kt & 1;
        if (kt + 1 < nkt) {
            ISSUE(kt + 1, buf ^ 1);
            asm volatile("cp.async.wait_group 1;" ::: "memory");
        } else {
            asm volatile("cp.async.wait_group 0;" ::: "memory");
        }
        __syncthreads();

        uint32_t bs = sb + buf * BUFSZ;
#pragma unroll
        for (int ks = 0; ks < 2; ks++) {
            uint32_t ah[2][4], al[2][4];
            uint32_t abase = bs + OFF_AH +
                             (uint32_t)((wm * 32 + g) * SAW + ks * 8 + c) * 4;
#pragma unroll
            for (int mt = 0; mt < 2; mt++) {
                uint32_t ab = abase + mt * 16 * SAW * 4;
                ah[mt][0] = lds32(ab);
                ah[mt][1] = lds32(ab + 8 * SAW * 4);
                ah[mt][2] = lds32(ab + 16);
                ah[mt][3] = lds32(ab + 8 * SAW * 4 + 16);
                uint32_t ab2 = ab + (OFF_AL - OFF_AH);
                al[mt][0] = lds32(ab2);
                al[mt][1] = lds32(ab2 + 8 * SAW * 4);
                al[mt][2] = lds32(ab2 + 16);
                al[mt][3] = lds32(ab2 + 8 * SAW * 4 + 16);
            }
            uint32_t bbase = bs + OFF_B +
                             (uint32_t)((wn * 64 + g) * SAW + ks * 8 + c) * 4;
#pragma unroll
            for (int nt = 0; nt < 8; nt++) {
                uint32_t bb = bbase + nt * 8 * SAW * 4;
                uint32_t b0 = lds32(bb), b1 = lds32(bb + 16);
#pragma unroll
                for (int mt = 0; mt < 2; mt++) {
                    mma16(acc[mt][nt], ah[mt], b0, b1);
                    mma16(acc[mt][nt], al[mt], b0, b1);
                }
            }
        }
        __syncthreads();
    }

#pragma unroll
    for (int mt = 0; mt < 2; mt++) {
        int rbase = m0 + wm * 32 + mt * 16 + g;
#pragma unroll
        for (int nt = 0; nt < 8; nt++) {
            int col = n0 + wn * 64 + nt * 8 + 2 * c;
            float b0v = bias[col], b1v = bias[col + 1];
#pragma unroll
            for (int rr = 0; rr < 2; rr++) {
                int r = rbase + rr * 8;
                float v0 = acc[mt][nt][rr * 2 + 0] + b0v;
                float v1 = acc[mt][nt][rr * 2 + 1] + b1v;
                if (GELU) { v0 = gelu_f(v0); v1 = gelu_f(v1); }
                if (RES) {
                    float2 rv = *(const float2*)(res + (size_t)r * N + col);
                    v0 += rv.x;
                    v1 += rv.y;
                }
                if (OUTM == 0) {
                    float2 ov; ov.x = v0; ov.y = v1;
                    *(float2*)(outf + (size_t)r * N + col) = ov;
                } else if (OUTM == 1) {
                    uint32_t hv = packh2(v0, v1);
                    *(uint32_t*)(outh + (size_t)r * N + col) = hv;
                } else {
                    f16 h0, l0, h1, l1;
                    split2(v0, h0, l0);
                    split2(v1, h1, l1);
                    __half2 hv; hv.x = h0; hv.y = h1;
                    __half2 lv; lv.x = l0; lv.y = l1;
                    *(__half2*)(outh + (size_t)r * N + col) = hv;
                    *(__half2*)(outl + (size_t)r * N + col) = lv;
                }
            }
        }
    }
}

// ---------------- flash attention (fp16 mma, fp32 accum) ----------------------
// grid (T/128, B*H), 256 threads (8 warps x 16 q-rows). key tile 64.
// smem: sQ[128][72], sK[64][72], sVt[64 d][72 keys]  (fp16, +8 pad)
#define ASM_HALVES (128 * 72 + 64 * 72 + 64 * 72)
#define ATTN_SMEM (ASM_HALVES * 2)

__global__ void __launch_bounds__(256) attn16_kernel(const f16* __restrict__ qkv,
                                                     f16* __restrict__ yh,
                                                     f16* __restrict__ yl) {
    extern __shared__ f16 sh[];
    f16* sQ = sh;                    // 128*72
    f16* sVt = sh + 128 * 72 + 64 * 72;
    const uint32_t sQa = smem_u32(sQ);
    const uint32_t sKa = sQa + 128 * 72 * 2;
    const uint32_t sVa = sKa + 64 * 72 * 2;

    const int qb = blockIdx.x;
    const int b = blockIdx.y / Hh, h = blockIdx.y % Hh;
    const int tid = threadIdx.x, lane = tid & 31, wid = tid >> 5;
    const int g = lane >> 2, c = lane & 3;
    const f16* base = qkv + (size_t)b * Tt * (3 * Cc) + h * Dd;

    // ---- load Q tile (128 x 64) ----
#pragma unroll
    for (int l = 0; l < 4; l++) {
        int ch = tid + l * 256;
        int r = ch >> 3, c8 = ch & 7;
        cp16(sQa + (uint32_t)(r * 72 + c8 * 8) * 2,
             base + (size_t)(qb * 128 + r) * (3 * Cc) + c8 * 8);
    }
    cp_commit();
    asm volatile("cp.async.wait_group 0;" ::: "memory");
    __syncthreads();

    // ---- Q fragments (held for whole kernel) ----
    uint32_t qf[4][4];
    {
        int row = wid * 16 + g;
        uint32_t a0 = sQa + (uint32_t)(row * 72) * 2;
        uint32_t a1 = sQa + (uint32_t)((row + 8) * 72) * 2;
#pragma unroll
        for (int t = 0; t < 4; t++) {
            uint32_t off = (uint32_t)(8 * t + c) * 4;
            qf[t][0] = lds32(a0 + off);
            qf[t][1] = lds32(a1 + off);
            qf[t][2] = lds32(a0 + off + 16);
            qf[t][3] = lds32(a1 + off + 16);
        }
    }

    float o[8][4];
#pragma unroll
    for (int j = 0; j < 8; j++)
#pragma unroll
        for (int r = 0; r < 4; r++) o[j][r] = 0.f;
    float mi0 = -1e30f, mi1 = -1e30f, li0 = 0.f, li1 = 0.f;
    const int row0 = qb * 128 + wid * 16 + g;
    const int row1 = row0 + 8;
    const int wqmax = qb * 128 + wid * 16 + 15;
    const int kbmax = 2 * qb + 1;

    for (int kb = 0; kb <= kbmax; kb++) {
        __syncthreads();  // previous compute done with sK/sVt
        // K tile (64 x 64)
#pragma unroll
        for (int l = 0; l < 2; l++) {
            int ch = tid + l * 256;
            int r = ch >> 3, c8 = ch & 7;
            cp16(sKa + (uint32_t)(r * 72 + c8 * 8) * 2,
                 base + (size_t)(kb * 64 + r) * (3 * Cc) + Cc + c8 * 8);
        }
        cp_commit();
        // V tile transposed into sVt[d][key]
        {
            int r = tid & 63, dq = tid >> 6;
            int dd0 = dq * 16;
            const f16* vp = base + (size_t)(kb * 64 + r) * (3 * Cc) + 2 * Cc + dd0;
            uint4 u0 = *(const uint4*)vp;
            uint4 u1 = *(const uint4*)(vp + 8);
            const f16* hb0 = (const f16*)&u0;
            const f16* hb1 = (const f16*)&u1;
#pragma unroll
            for (int i = 0; i < 8; i++) sVt[(dd0 + i) * 72 + r] = hb0[i];
#pragma unroll
            for (int i = 0; i < 8; i++) sVt[(dd0 + 8 + i) * 72 + r] = hb1[i];
        }
        asm volatile("cp.async.wait_group 0;" ::: "memory");
        __syncthreads();

        if (kb * 64 <= wqmax) {
            // S = Q K^T
            float s[8][4];
#pragma unroll
            for (int j = 0; j < 8; j++)
#pragma unroll
                for (int r = 0; r < 4; r++) s[j][r] = 0.f;
#pragma unroll
            for (int j = 0; j < 8; j++) {
                uint32_t bb = sKa + (uint32_t)((8 * j + g) * 72) * 2;
#pragma unroll
                for (int t = 0; t < 4; t++) {
                    uint32_t off = (uint32_t)(8 * t + c) * 4;
                    uint32_t b0 = lds32(bb + off), b1 = lds32(bb + off + 16);
                    mma16(s[j], qf[t], b0, b1);
                }
            }
            // scale + mask
            const bool doMask = (kb * 64 + 63) > (qb * 128 + wid * 16);
#pragma unroll
            for (int j = 0; j < 8; j++) {
                int col = kb * 64 + 8 * j + 2 * c;
                s[j][0] *= 0.125f; s[j][1] *= 0.125f;
                s[j][2] *= 0.125f; s[j][3] *= 0.125f;
                if (doMask) {
                    if (col > row0) s[j][0] = -1e30f;
                    if (col + 1 > row0) s[j][1] = -1e30f;
                    if (col > row1) s[j][2] = -1e30f;
                    if (col + 1 > row1) s[j][3] = -1e30f;
                }
            }
            // online softmax (rows row0, row1)
            float rm0 = -1e30f, rm1 = -1e30f;
#pragma unroll
            for (int j = 0; j < 8; j++) {
                rm0 = fmaxf(rm0, fmaxf(s[j][0], s[j][1]));
                rm1 = fmaxf(rm1, fmaxf(s[j][2], s[j][3]));
            }
            rm0 = fmaxf(rm0, __shfl_xor_sync(0xffffffffu, rm0, 1));
            rm0 = fmaxf(rm0, __shfl_xor_sync(0xffffffffu, rm0, 2));
            rm1 = fmaxf(rm1, __shfl_xor_sync(0xffffffffu, rm1, 1));
            rm1 = fmaxf(rm1, __shfl_xor_sync(0xffffffffu, rm1, 2));
            float mn0 = fmaxf(mi0, rm0), mn1 = fmaxf(mi1, rm1);
            float al0 = __expf(mi0 - mn0), al1 = __expf(mi1 - mn1);
            float rs0 = 0.f, rs1 = 0.f;
#pragma unroll
            for (int j = 0; j < 8; j++) {
                s[j][0] = __expf(s[j][0] - mn0);
                s[j][1] = __expf(s[j][1] - mn0);
                s[j][2] = __expf(s[j][2] - mn1);
                s[j][3] = __expf(s[j][3] - mn1);
                rs0 += s[j][0] + s[j][1];
                rs1 += s[j][2] + s[j][3];
            }
            rs0 += __shfl_xor_sync(0xffffffffu, rs0, 1);
            rs0 += __shfl_xor_sync(0xffffffffu, rs0, 2);
            rs1 += __shfl_xor_sync(0xffffffffu, rs1, 1);
            rs1 += __shfl_xor_sync(0xffffffffu, rs1, 2);
            li0 = li0 * al0 + rs0;
            li1 = li1 * al1 + rs1;
            mi0 = mn0; mi1 = mn1;
#pragma unroll
            for (int j = 0; j < 8; j++) {
                o[j][0] *= al0; o[j][1] *= al0;
                o[j][2] *= al1; o[j][3] *= al1;
            }
            // O += P @ V  (P from regs)
#pragma unroll
            for (int t = 0; t < 4; t++) {
                uint32_t pa[4];
                pa[0] = packh2(s[2 * t][0], s[2 * t][1]);
                pa[1] = packh2(s[2 * t][2], s[2 * t][3]);
                pa[2] = packh2(s[2 * t + 1][0], s[2 * t + 1][1]);
                pa[3] = packh2(s[2 * t + 1][2], s[2 * t + 1][3]);
#pragma unroll
                for (int j = 0; j < 8; j++) {
                    uint32_t bb = sVa + (uint32_t)((8 * j + g) * 72) * 2;
                    uint32_t off = (uint32_t)(8 * t + c) * 4;
                    uint32_t b0 = lds32(bb + off), b1 = lds32(bb + off + 16);
                    mma16(o[j], pa, b0, b1);
                }
            }
        }
    }

    // ---- epilogue: y = O / li, split fp16 hi/lo ----
    float inv0 = 1.f / li0, inv1 = 1.f / li1;
    size_t rb0 = ((size_t)b * Tt + qb * 128 + wid * 16 + g) * Cc + h * Dd;
    size_t rb1 = rb0 + (size_t)8 * Cc;
#pragma unroll
    for (int j = 0; j < 8; j++) {
        int col = 8 * j + 2 * c;
        f16 h0, l0, h1, l1;
        split2(o[j][0] * inv0, h0, l0);
        split2(o[j][1] * inv0, h1, l1);
        __half2 hv; hv.x = h0; hv.y = h1;
        __half2 lv; lv.x = l0; lv.y = l1;
        *(__half2*)(yh + rb0 + col) = hv;
        *(__half2*)(yl + rb0 + col) = lv;
        split2(o[j][2] * inv1, h0, l0);
        split2(o[j][3] * inv1, h1, l1);
        hv.x = h0; hv.y = h1;
        lv.x = l0; lv.y = l1;
        *(__half2*)(yh + rb1 + col) = hv;
        *(__half2*)(yl + rb1 + col) = lv;
    }
}

// ---------------- final LN + head matvec --------------------------------------
__global__ void head_kernel(const float* __restrict__ x, const float* __restrict__ w,
                            const float* __restrict__ b, const float* __restrict__ wh,
                            float* __restrict__ out) {
    int row = blockIdx.x;
    int t = threadIdx.x;
    const float* xr = x + (size_t)row * Cc;
    float v[3];
    float s = 0.f, s2 = 0.f;
#pragma unroll
    for (int i = 0; i < 3; i++) { v[i] = xr[t + i * 256]; s += v[i]; s2 += v[i] * v[i]; }
#pragma unroll
    for (int m = 16; m; m >>= 1) {
        s  += __shfl_xor_sync(0xffffffffu, s, m);
        s2 += __shfl_xor_sync(0xffffffffu, s2, m);
    }
    __shared__ float rs[8], rs2[8], rd[8];
    if ((t & 31) == 0) { rs[t >> 5] = s; rs2[t >> 5] = s2; }
    __syncthreads();
    s = 0.f; s2 = 0.f;
#pragma unroll
    for (int i = 0; i < 8; i++) { s += rs[i]; s2 += rs2[i]; }
    float mu = s * (1.0f / Cc);
    float var = s2 * (1.0f / Cc) - mu * mu;
    float rstd = rsqrtf(var + 1e-5f);
    float dot = 0.f;
#pragma unroll
    for (int i = 0; i < 3; i++) {
        int c = t + i * 256;
        dot += ((v[i] - mu) * rstd * w[c] + b[c]) * wh[c];
    }
#pragma unroll
    for (int m = 16; m; m >>= 1) dot += __shfl_xor_sync(0xffffffffu, dot, m);
    if ((t & 31) == 0) rd[t >> 5] = dot;
    __syncthreads();
    if (t == 0) {
        float d = 0.f;
#pragma unroll
        for (int i = 0; i < 8; i++) d += rd[i];
        out[row] = d;
    }
}

// ---------------- host launch --------------------------------------------------
extern "C" void kernel_launch(void* const* d_in, const int* in_sizes, int n_in,
                              void* d_out, int out_size) {
    (void)in_sizes; (void)n_in; (void)out_size;
    const int*   idx   = (const int*)d_in[0];
    const float* wte   = (const float*)d_in[1];
    const float* wpe   = (const float*)d_in[2];
    const float* ln1w  = (const float*)d_in[3];
    const float* ln1b  = (const float*)d_in[4];
    const float* wqkv  = (const float*)d_in[5];
    const float* bqkv  = (const float*)d_in[6];
    const float* wao   = (const float*)d_in[7];
    const float* bao   = (const float*)d_in[8];
    const float* ln2w  = (const float*)d_in[9];
    const float* ln2b  = (const float*)d_in[10];
    const float* wfc   = (const float*)d_in[11];
    const float* bfc   = (const float*)d_in[12];
    const float* wfp   = (const float*)d_in[13];
    const float* bfp   = (const float*)d_in[14];
    const float* lnfw  = (const float*)d_in[15];
    const float* lnfb  = (const float*)d_in[16];
    const float* whead = (const float*)d_in[17];

    float* x;
    f16 *qkv16, *hh, *hl, *yh, *yl, *ffh, *ffl;
    f16 *wqkvT, *waoT, *wfcT, *wfpT;
    cudaGetSymbolAddress((void**)&x, g_x);
    cudaGetSymbolAddress((void**)&qkv16, g_qkv16);
    cudaGetSymbolAddress((void**)&hh, g_hh);
    cudaGetSymbolAddress((void**)&hl, g_hl);
    cudaGetSymbolAddress((void**)&yh, g_yh);
    cudaGetSymbolAddress((void**)&yl, g_yl);
    cudaGetSymbolAddress((void**)&ffh, g_ffh);
    cudaGetSymbolAddress((void**)&ffl, g_ffl);
    cudaGetSymbolAddress((void**)&wqkvT, g_wqkvT);
    cudaGetSymbolAddress((void**)&waoT, g_waoT);
    cudaGetSymbolAddress((void**)&wfcT, g_wfcT);
    cudaGetSymbolAddress((void**)&wfpT, g_wfpT);

    cudaFuncSetAttribute((const void*)attn16_kernel,
                         cudaFuncAttributeMaxDynamicSharedMemorySize, ATTN_SMEM);
    cudaFuncSetAttribute((const void*)gemm_mma<false, false, 1>,
                         cudaFuncAttributeMaxDynamicSharedMemorySize, GSM2);
    cudaFuncSetAttribute((const void*)gemm_mma<false, true, 0>,
                         cudaFuncAttributeMaxDynamicSharedMemorySize, GSM2);
    cudaFuncSetAttribute((const void*)gemm_mma<true, false, 2>,
                         cudaFuncAttributeMaxDynamicSharedMemorySize, GSM2);

    for (int l = 0; l < Ll; l++) {
        wsplit_kernel<<<dim3(3 * Cc / 32, Cc / 32), 256>>>(
            wqkv + (size_t)l * Cc * 3 * Cc, wqkvT + (size_t)l * 3 * Cc * Cc, Cc, 3 * Cc);
        wsplit_kernel<<<dim3(Cc / 32, Cc / 32), 256>>>(
            wao + (size_t)l * Cc * Cc, waoT + (size_t)l * Cc * Cc, Cc, Cc);
        wsplit_kernel<<<dim3(4 * Cc / 32, Cc / 32), 256>>>(
            wfc + (size_t)l * Cc * 4 * Cc, wfcT + (size_t)l * 4 * Cc * Cc, Cc, 4 * Cc);
        wsplit_kernel<<<dim3(Cc / 32, 4 * Cc / 32), 256>>>(
            wfp + (size_t)l * 4 * Cc * Cc, wfpT + (size_t)l * Cc * 4 * Cc, 4 * Cc, Cc);
    }

    embed_kernel<<<BT, 192>>>(idx, wte, wpe, x);

    for (int l = 0; l < Ll; l++) {
        ln_kernel<<<BT, 256>>>(x, ln1w + l * Cc, ln1b + l * Cc, hh, hl);
        gemm_mma<false, false, 1><<<dim3(18, 32), 256, GSM2>>>(
            hh, hl, wqkvT + (size_t)l * 3 * Cc * Cc, bqkv + l * 3 * Cc,
            nullptr, nullptr, qkv16, nullptr, BT, 3 * Cc, Cc);
        attn16_kernel<<<dim3(Tt / 128, Bq * Hh), 256, ATTN_SMEM>>>(qkv16, yh, yl);
        gemm_mma<false, true, 0><<<dim3(6, 32), 256, GSM2>>>(
            yh, yl, waoT + (size_t)l * Cc * Cc, bao + l * Cc,
            x, x, nullptr, nullptr, BT, Cc, Cc);
        ln_kernel<<<BT, 256>>>(x, ln2w + l * Cc, ln2b + l * Cc, hh, hl);
        gemm_mma<true, false, 2><<<dim3(24, 32), 256, GSM2>>>(
            hh, hl, wfcT + (size_t)l * 4 * Cc * Cc, bfc + l * 4 * Cc,
            nullptr, nullptr, ffh, ffl, BT, 4 * Cc, Cc);
        gemm_mma<false, true, 0><<<dim3(6, 32), 256, GSM2>>>(
            ffh, ffl, wfpT + (size_t)l * Cc * 4 * Cc, bfp + l * Cc,
            x, x, nullptr, nullptr, BT, Cc, 4 * Cc);
    }

    head_kernel<<<BT, 256>>>(x, lnfw, lnfb, whead, (float*)d_out);
}

// round 5
// speedup vs baseline: 3.9425x; 1.2103x over previous
#include <cuda_runtime.h>
#include <cuda_fp16.h>
#include <math.h>
#include <stdint.h>

#define Bq 4
#define Tt 1024
#define Cc 768
#define Hh 12
#define Dd 64
#define Ll 12
#define BT 4096

typedef __half f16;

// ---------------- scratch (device globals) ------------------------------------
__device__ __align__(16) float g_x[BT * Cc];
__device__ __align__(16) f16 g_qkv16[BT * 3 * Cc];

__device__ __align__(16) f16 g_hh[BT * Cc];
__device__ __align__(16) f16 g_hl[BT * Cc];
__device__ __align__(16) f16 g_yh[BT * Cc];
__device__ __align__(16) f16 g_yl[BT * Cc];
__device__ __align__(16) f16 g_ffh[BT * 4 * Cc];
__device__ __align__(16) f16 g_ffl[BT * 4 * Cc];

__device__ __align__(16) f16 g_wqkvT[Ll * 3 * Cc * Cc];
__device__ __align__(16) f16 g_waoT[Ll * Cc * Cc];
__device__ __align__(16) f16 g_wfcT[Ll * 4 * Cc * Cc];
__device__ __align__(16) f16 g_wfpT[Ll * Cc * 4 * Cc];

// ---------------- helpers -----------------------------------------------------
__device__ __forceinline__ uint32_t smem_u32(const void* p) {
    uint32_t a;
    asm("{ .reg .u64 t; cvta.to.shared.u64 t, %1; cvt.u32.u64 %0, t; }"
        : "=r"(a) : "l"(p));
    return a;
}
__device__ __forceinline__ void ldsm4(uint32_t* r, uint32_t addr) {
    asm volatile("ldmatrix.sync.aligned.m8n8.x4.shared.b16 {%0,%1,%2,%3}, [%4];"
                 : "=r"(r[0]), "=r"(r[1]), "=r"(r[2]), "=r"(r[3]) : "r"(addr));
}
__device__ __forceinline__ void cp16(uint32_t dst, const void* src) {
    asm volatile("cp.async.ca.shared.global [%0], [%1], 16;"
                 :: "r"(dst), "l"(src) : "memory");
}
__device__ __forceinline__ void cp_commit() {
    asm volatile("cp.async.commit_group;" ::: "memory");
}
__device__ __forceinline__ void mma16(float* c, const uint32_t* a,
                                      uint32_t b0, uint32_t b1) {
    asm volatile(
        "mma.sync.aligned.m16n8k16.row.col.f32.f16.f16.f32 "
        "{%0,%1,%2,%3}, {%4,%5,%6,%7}, {%8,%9}, {%0,%1,%2,%3};"
        : "+f"(c[0]), "+f"(c[1]), "+f"(c[2]), "+f"(c[3])
        : "r"(a[0]), "r"(a[1]), "r"(a[2]), "r"(a[3]), "r"(b0), "r"(b1));
}
__device__ __forceinline__ void split2(float f, f16& h, f16& l) {
    h = __float2half_rn(f);
    l = __float2half_rn(f - __half2float(h));
}
__device__ __forceinline__ float gelu_f(float x) {
    float x3 = x * x * x;
    return 0.5f * x * (1.f + tanhf(0.7978845608028654f * (x + 0.044715f * x3)));
}
__device__ __forceinline__ uint32_t packh2(float a, float b) {
    __half2 h = __floats2half2_rn(a, b);
    return *(uint32_t*)&h;
}

// ---------------- weight transpose to fp16 (batched over layers) ---------------
__global__ void wsplit_kernel(const float* __restrict__ W, f16* __restrict__ Th,
                              int K, int N) {
    __shared__ float t[32][33];
    size_t loff = (size_t)blockIdx.z * K * N;
    const float* Wl = W + loff;
    f16* Tl = Th + loff;
    int n0 = blockIdx.x * 32, k0 = blockIdx.y * 32;
    int tx = threadIdx.x & 31, ty = threadIdx.x >> 5;
#pragma unroll
    for (int j = 0; j < 4; j++)
        t[ty + 8 * j][tx] = Wl[(size_t)(k0 + ty + 8 * j) * N + n0 + tx];
    __syncthreads();
#pragma unroll
    for (int j = 0; j < 4; j++) {
        int nr = ty + 8 * j;
        Tl[(size_t)(n0 + nr) * K + k0 + tx] = __float2half_rn(t[tx][nr]);
    }
}

// ---------------- embedding ---------------------------------------------------
__global__ void embed_kernel(const int* __restrict__ idx, const float* __restrict__ wte,
                             const float* __restrict__ wpe, float* __restrict__ x) {
    int row = blockIdx.x;
    int tok = idx[row];
    int t = row & (Tt - 1);
    int c = threadIdx.x * 4;
    float4 a = *(const float4*)(wte + (size_t)tok * Cc + c);
    float4 p = *(const float4*)(wpe + (size_t)t * Cc + c);
    a.x += p.x; a.y += p.y; a.z += p.z; a.w += p.w;
    *(float4*)(x + (size_t)row * Cc + c) = a;
}

// ---------------- layernorm (fp32 in, hi/lo fp16 out) -------------------------
__global__ void ln_kernel(const float* __restrict__ in, const float* __restrict__ w,
                          const float* __restrict__ b, f16* __restrict__ oh,
                          f16* __restrict__ ol) {
    int row = blockIdx.x;
    int t = threadIdx.x;
    const float* xr = in + (size_t)row * Cc;
    float v[3];
    float s = 0.f, s2 = 0.f;
#pragma unroll
    for (int i = 0; i < 3; i++) { v[i] = xr[t + i * 256]; s += v[i]; s2 += v[i] * v[i]; }
#pragma unroll
    for (int m = 16; m; m >>= 1) {
        s  += __shfl_xor_sync(0xffffffffu, s, m);
        s2 += __shfl_xor_sync(0xffffffffu, s2, m);
    }
    __shared__ float rs[8], rs2[8];
    if ((t & 31) == 0) { rs[t >> 5] = s; rs2[t >> 5] = s2; }
    __syncthreads();
    s = 0.f; s2 = 0.f;
#pragma unroll
    for (int i = 0; i < 8; i++) { s += rs[i]; s2 += rs2[i]; }
    float mu = s * (1.0f / Cc);
    float var = s2 * (1.0f / Cc) - mu * mu;
    float rstd = rsqrtf(var + 1e-5f);
#pragma unroll
    for (int i = 0; i < 3; i++) {
        int c = t + i * 256;
        float o = (v[i] - mu) * rstd * w[c] + b[c];
        f16 h, l;
        split2(o, h, l);
        oh[(size_t)row * Cc + c] = h;
        ol[(size_t)row * Cc + c] = l;
    }
}

// ---------------- GEMM via mma.sync fp16 split-2, ldmatrix, 3-stage ------------
#define SAW 20
#define OFF_AH 0u
#define OFF_AL 10240u
#define OFF_B  20480u
#define BUFSZ  30720u
#define GSM3   (3 * 30720)

// OUTM: 0 = fp32 out (+res opt), 1 = fp16 single out, 2 = fp16 hi/lo out
template <bool GELU, bool RES, int OUTM>
__global__ void __launch_bounds__(256) gemm_mma(
    const f16* __restrict__ Ah, const f16* __restrict__ Al,
    const f16* __restrict__ B,
    const float* __restrict__ bias, const float* __restrict__ res,
    float* __restrict__ outf, f16* __restrict__ outh, f16* __restrict__ outl,
    int M, int N, int K) {
    extern __shared__ char smem[];
    const uint32_t sb = smem_u32(smem);
    const int tid = threadIdx.x;
    const int lane = tid & 31, wid = tid >> 5;
    const int g = lane >> 2, c = lane & 3;
    const int wm = wid & 3, wn = wid >> 2;
    const int m0 = blockIdx.y * 128, n0 = blockIdx.x * 128;

    const int r_ld = tid >> 2;
    const int q_ld = tid & 3;
    const uint32_t d0 = (uint32_t)(r_ld * SAW + q_ld * 4) * 4;
    const uint32_t d1 = (uint32_t)((r_ld + 64) * SAW + q_ld * 4) * 4;

    // per-lane ldmatrix offsets (bytes)
    const int tl = lane >> 3, rw = lane & 7;
    const uint32_t aoff = (uint32_t)(((tl & 1) * 8 + rw) * SAW * 4 + (tl >> 1) * 16);
    const uint32_t boff = (uint32_t)(((tl >> 1) * 8 + rw) * SAW * 4 + (tl & 1) * 16);

    float acc[2][8][4];
#pragma unroll
    for (int mt = 0; mt < 2; mt++)
#pragma unroll
        for (int nt = 0; nt < 8; nt++)
#pragma unroll
            for (int r = 0; r < 4; r++) acc[mt][nt][r] = 0.f;

    const int nkt = K >> 5;

#define ISSUE(KT, BUF)                                                          \
    do {                                                                        \
        uint32_t bs = sb + (BUF) * BUFSZ;                                       \
        size_t ka = (size_t)(m0 + r_ld) * K + (KT) * 32 + q_ld * 8;             \
        size_t kb = (size_t)(n0 + r_ld) * K + (KT) * 32 + q_ld * 8;             \
        cp16(bs + OFF_AH + d0, Ah + ka);                                        \
        cp16(bs + OFF_AH + d1, Ah + ka + (size_t)64 * K);                       \
        cp16(bs + OFF_AL + d0, Al + ka);                                        \
        cp16(bs + OFF_AL + d1, Al + ka + (size_t)64 * K);                       \
        cp16(bs + OFF_B + d0, B + kb);                                          \
        cp16(bs + OFF_B + d1, B + kb + (size_t)64 * K);                         \
        cp_commit();                                                            \
    } while (0)

    ISSUE(0, 0);
    ISSUE(1, 1);

    for (int kt = 0; kt < nkt; kt++) {
        if (kt + 1 < nkt)
            asm volatile("cp.async.wait_group 1;" ::: "memory");
        else
            asm volatile("cp.async.wait_group 0;" ::: "memory");
        __syncthreads();
        if (kt + 2 < nkt) {
            int b2 = (kt + 2) % 3;
            ISSUE(kt + 2, b2);
        }

        uint32_t bs = sb + (uint32_t)(kt % 3) * BUFSZ;
        uint32_t abase = bs + aoff + (uint32_t)(wm * 32) * SAW * 4;
        uint32_t bbase = bs + OFF_B + boff + (uint32_t)(wn * 64) * SAW * 4;
#pragma unroll
        for (int ks = 0; ks < 2; ks++) {
            uint32_t ah[2][4], al[2][4];
#pragma unroll
            for (int mt = 0; mt < 2; mt++) {
                uint32_t ar = abase + (uint32_t)(mt * 16) * SAW * 4 + ks * 32;
                ldsm4(ah[mt], ar + OFF_AH);
                ldsm4(al[mt], ar + OFF_AL);
            }
#pragma unroll
            for (int jj = 0; jj < 4; jj++) {
                uint32_t bf[4];
                ldsm4(bf, bbase + (uint32_t)(jj * 16) * SAW * 4 + ks * 32);
#pragma unroll
                for (int mt = 0; mt < 2; mt++) {
                    mma16(acc[mt][2 * jj], ah[mt], bf[0], bf[1]);
                    mma16(acc[mt][2 * jj], al[mt], bf[0], bf[1]);
                    mma16(acc[mt][2 * jj + 1], ah[mt], bf[2], bf[3]);
                    mma16(acc[mt][2 * jj + 1], al[mt], bf[2], bf[3]);
                }
            }
        }
    }

#pragma unroll
    for (int mt = 0; mt < 2; mt++) {
        int rbase = m0 + wm * 32 + mt * 16 + g;
#pragma unroll
        for (int nt = 0; nt < 8; nt++) {
            int col = n0 + wn * 64 + nt * 8 + 2 * c;
            float b0v = bias[col], b1v = bias[col + 1];
#pragma unroll
            for (int rr = 0; rr < 2; rr++) {
                int r = rbase + rr * 8;
                float v0 = acc[mt][nt][rr * 2 + 0] + b0v;
                float v1 = acc[mt][nt][rr * 2 + 1] + b1v;
                if (GELU) { v0 = gelu_f(v0); v1 = gelu_f(v1); }
                if (RES) {
                    float2 rv = *(const float2*)(res + (size_t)r * N + col);
                    v0 += rv.x;
                    v1 += rv.y;
                }
                if (OUTM == 0) {
                    float2 ov; ov.x = v0; ov.y = v1;
                    *(float2*)(outf + (size_t)r * N + col) = ov;
                } else if (OUTM == 1) {
                    uint32_t hv = packh2(v0, v1);
                    *(uint32_t*)(outh + (size_t)r * N + col) = hv;
                } else {
                    f16 h0, l0, h1, l1;
                    split2(v0, h0, l0);
                    split2(v1, h1, l1);
                    __half2 hv; hv.x = h0; hv.y = h1;
                    __half2 lv; lv.x = l0; lv.y = l1;
                    *(__half2*)(outh + (size_t)r * N + col) = hv;
                    *(__half2*)(outl + (size_t)r * N + col) = lv;
                }
            }
        }
    }
}

// ---------------- flash attention (fp16 mma, ldmatrix fragments) ---------------
#define ASM_HALVES (128 * 72 + 64 * 72 + 64 * 72)
#define ATTN_SMEM (ASM_HALVES * 2)

__global__ void __launch_bounds__(256) attn16_kernel(const f16* __restrict__ qkv,
                                                     f16* __restrict__ yh,
                                                     f16* __restrict__ yl) {
    extern __shared__ f16 sh[];
    f16* sVt = sh + 128 * 72 + 64 * 72;
    const uint32_t sQa = smem_u32(sh);
    const uint32_t sKa = sQa + 128 * 72 * 2;
    const uint32_t sVa = sKa + 64 * 72 * 2;

    const int qb = blockIdx.x;
    const int b = blockIdx.y / Hh, h = blockIdx.y % Hh;
    const int tid = threadIdx.x, lane = tid & 31, wid = tid >> 5;
    const int g = lane >> 2, c = lane & 3;
    const int tl = lane >> 3, rw = lane & 7;
    const f16* base = qkv + (size_t)b * Tt * (3 * Cc) + h * Dd;

    // ldmatrix per-lane offsets (bytes), row stride 144 = 72 halves
    const uint32_t aoff = (uint32_t)(((tl & 1) * 8 + rw) * 72 + (tl >> 1) * 8) * 2;
    const uint32_t boff = (uint32_t)(((tl >> 1) * 8 + rw) * 72 + (tl & 1) * 8) * 2;

    // ---- load Q tile (128 x 64) ----
#pragma unroll
    for (int l = 0; l < 4; l++) {
        int ch = tid + l * 256;
        int r = ch >> 3, c8 = ch & 7;
        cp16(sQa + (uint32_t)(r * 72 + c8 * 8) * 2,
             base + (size_t)(qb * 128 + r) * (3 * Cc) + c8 * 8);
    }
    cp_commit();
    asm volatile("cp.async.wait_group 0;" ::: "memory");
    __syncthreads();

    // ---- Q fragments ----
    uint32_t qf[4][4];
    {
        uint32_t qa = sQa + (uint32_t)(wid * 16) * 144 + aoff;
#pragma unroll
        for (int t = 0; t < 4; t++) ldsm4(qf[t], qa + t * 32);
    }

    float o[8][4];
#pragma unroll
    for (int j = 0; j < 8; j++)
#pragma unroll
        for (int r = 0; r < 4; r++) o[j][r] = 0.f;
    float mi0 = -1e30f, mi1 = -1e30f, li0 = 0.f, li1 = 0.f;
    const int row0 = qb * 128 + wid * 16 + g;
    const int row1 = row0 + 8;
    const int wqmax = qb * 128 + wid * 16 + 15;
    const int kbmax = 2 * qb + 1;

    for (int kb = 0; kb <= kbmax; kb++) {
        __syncthreads();
#pragma unroll
        for (int l = 0; l < 2; l++) {
            int ch = tid + l * 256;
            int r = ch >> 3, c8 = ch & 7;
            cp16(sKa + (uint32_t)(r * 72 + c8 * 8) * 2,
                 base + (size_t)(kb * 64 + r) * (3 * Cc) + Cc + c8 * 8);
        }
        cp_commit();
        {
            int r = tid & 63, dq = tid >> 6;
            int dd0 = dq * 16;
            const f16* vp = base + (size_t)(kb * 64 + r) * (3 * Cc) + 2 * Cc + dd0;
            uint4 u0 = *(const uint4*)vp;
            uint4 u1 = *(const uint4*)(vp + 8);
            const f16* hb0 = (const f16*)&u0;
            const f16* hb1 = (const f16*)&u1;
#pragma unroll
            for (int i = 0; i < 8; i++) sVt[(dd0 + i) * 72 + r] = hb0[i];
#pragma unroll
            for (int i = 0; i < 8; i++) sVt[(dd0 + 8 + i) * 72 + r] = hb1[i];
        }
        asm volatile("cp.async.wait_group 0;" ::: "memory");
        __syncthreads();

        if (kb * 64 <= wqmax) {
            // S = Q K^T
            float s[8][4];
#pragma unroll
            for (int j = 0; j < 8; j++)
#pragma unroll
                for (int r = 0; r < 4; r++) s[j][r] = 0.f;
#pragma unroll
            for (int jj = 0; jj < 4; jj++) {
                uint32_t kbse = sKa + boff + (uint32_t)(jj * 16) * 144;
#pragma unroll
                for (int t = 0; t < 4; t++) {
                    uint32_t kf[4];
                    ldsm4(kf, kbse + t * 32);
                    mma16(s[2 * jj], qf[t], kf[0], kf[1]);
                    mma16(s[2 * jj + 1], qf[t], kf[2], kf[3]);
                }
            }
            // scale + mask
            const bool doMask = (kb * 64 + 63) > (qb * 128 + wid * 16);
#pragma unroll
            for (int j = 0; j < 8; j++) {
                int col = kb * 64 + 8 * j + 2 * c;
                s[j][0] *= 0.125f; s[j][1] *= 0.125f;
                s[j][2] *= 0.125f; s[j][3] *= 0.125f;
                if (doMask) {
                    if (col > row0) s[j][0] = -1e30f;
                    if (col + 1 > row0) s[j][1] = -1e30f;
                    if (col > row1) s[j][2] = -1e30f;
                    if (col + 1 > row1) s[j][3] = -1e30f;
                }
            }
            // online softmax
            float rm0 = -1e30f, rm1 = -1e30f;
#pragma unroll
            for (int j = 0; j < 8; j++) {
                rm0 = fmaxf(rm0, fmaxf(s[j][0], s[j][1]));
                rm1 = fmaxf(rm1, fmaxf(s[j][2], s[j][3]));
            }
            rm0 = fmaxf(rm0, __shfl_xor_sync(0xffffffffu, rm0, 1));
            rm0 = fmaxf(rm0, __shfl_xor_sync(0xffffffffu, rm0, 2));
            rm1 = fmaxf(rm1, __shfl_xor_sync(0xffffffffu, rm1, 1));
            rm1 = fmaxf(rm1, __shfl_xor_sync(0xffffffffu, rm1, 2));
            float mn0 = fmaxf(mi0, rm0), mn1 = fmaxf(mi1, rm1);
            float al0 = __expf(mi0 - mn0), al1 = __expf(mi1 - mn1);
            float rs0 = 0.f, rs1 = 0.f;
#pragma unroll
            for (int j = 0; j < 8; j++) {
                s[j][0] = __expf(s[j][0] - mn0);
                s[j][1] = __expf(s[j][1] - mn0);
                s[j][2] = __expf(s[j][2] - mn1);
                s[j][3] = __expf(s[j][3] - mn1);
                rs0 += s[j][0] + s[j][1];
                rs1 += s[j][2] + s[j][3];
            }
            rs0 += __shfl_xor_sync(0xffffffffu, rs0, 1);
            rs0 += __shfl_xor_sync(0xffffffffu, rs0, 2);
            rs1 += __shfl_xor_sync(0xffffffffu, rs1, 1);
            rs1 += __shfl_xor_sync(0xffffffffu, rs1, 2);
            li0 = li0 * al0 + rs0;
            li1 = li1 * al1 + rs1;
            mi0 = mn0; mi1 = mn1;
#pragma unroll
            for (int j = 0; j < 8; j++) {
                o[j][0] *= al0; o[j][1] *= al0;
                o[j][2] *= al1; o[j][3] *= al1;
            }
            // pack P fragments
            uint32_t pa[4][4];
#pragma unroll
            for (int t = 0; t < 4; t++) {
                pa[t][0] = packh2(s[2 * t][0], s[2 * t][1]);
                pa[t][1] = packh2(s[2 * t][2], s[2 * t][3]);
                pa[t][2] = packh2(s[2 * t + 1][0], s[2 * t + 1][1]);
                pa[t][3] = packh2(s[2 * t + 1][2], s[2 * t + 1][3]);
            }
            // O += P @ V
#pragma unroll
            for (int jj = 0; jj < 4; jj++) {
                uint32_t vbse = sVa + boff + (uint32_t)(jj * 16) * 144;
#pragma unroll
                for (int t = 0; t < 4; t++) {
                    uint32_t vf[4];
                    ldsm4(vf, vbse + t * 32);
                    mma16(o[2 * jj], pa[t], vf[0], vf[1]);
                    mma16(o[2 * jj + 1], pa[t], vf[2], vf[3]);
                }
            }
        }
    }

    // ---- epilogue ----
    float inv0 = 1.f / li0, inv1 = 1.f / li1;
    size_t rb0 = ((size_t)b * Tt + qb * 128 + wid * 16 + g) * Cc + h * Dd;
    size_t rb1 = rb0 + (size_t)8 * Cc;
#pragma unroll
    for (int j = 0; j < 8; j++) {
        int col = 8 * j + 2 * c;
        f16 h0, l0, h1, l1;
        split2(o[j][0] * inv0, h0, l0);
        split2(o[j][1] * inv0, h1, l1);
        __half2 hv; hv.x = h0; hv.y = h1;
        __half2 lv; lv.x = l0; lv.y = l1;
        *(__half2*)(yh + rb0 + col) = hv;
        *(__half2*)(yl + rb0 + col) = lv;
        split2(o[j][2] * inv1, h0, l0);
        split2(o[j][3] * inv1, h1, l1);
        hv.x = h0; hv.y = h1;
        lv.x = l0; lv.y = l1;
        *(__half2*)(yh + rb1 + col) = hv;
        *(__half2*)(yl + rb1 + col) = lv;
    }
}

// ---------------- final LN + head matvec --------------------------------------
__global__ void head_kernel(const float* __restrict__ x, const float* __restrict__ w,
                            const float* __restrict__ b, const float* __restrict__ wh,
                            float* __restrict__ out) {
    int row = blockIdx.x;
    int t = threadIdx.x;
    const float* xr = x + (size_t)row * Cc;
    float v[3];
    float s = 0.f, s2 = 0.f;
#pragma unroll
    for (int i = 0; i < 3; i++) { v[i] = xr[t + i * 256]; s += v[i]; s2 += v[i] * v[i]; }
#pragma unroll
    for (int m = 16; m; m >>= 1) {
        s  += __shfl_xor_sync(0xffffffffu, s, m);
        s2 += __shfl_xor_sync(0xffffffffu, s2, m);
    }
    __shared__ float rs[8], rs2[8], rd[8];
    if ((t & 31) == 0) { rs[t >> 5] = s; rs2[t >> 5] = s2; }
    __syncthreads();
    s = 0.f; s2 = 0.f;
#pragma unroll
    for (int i = 0; i < 8; i++) { s += rs[i]; s2 += rs2[i]; }
    float mu = s * (1.0f / Cc);
    float var = s2 * (1.0f / Cc) - mu * mu;
    float rstd = rsqrtf(var + 1e-5f);
    float dot = 0.f;
#pragma unroll
    for (int i = 0; i < 3; i++) {
        int c = t + i * 256;
        dot += ((v[i] - mu) * rstd * w[c] + b[c]) * wh[c];
    }
#pragma unroll
    for (int m = 16; m; m >>= 1) dot += __shfl_xor_sync(0xffffffffu, dot, m);
    if ((t & 31) == 0) rd[t >> 5] = dot;
    __syncthreads();
    if (t == 0) {
        float d = 0.f;
#pragma unroll
        for (int i = 0; i < 8; i++) d += rd[i];
        out[row] = d;
    }
}

// ---------------- host launch --------------------------------------------------
extern "C" void kernel_launch(void* const* d_in, const int* in_sizes, int n_in,
                              void* d_out, int out_size) {
    (void)in_sizes; (void)n_in; (void)out_size;
    const int*   idx   = (const int*)d_in[0];
    const float* wte   = (const float*)d_in[1];
    const float* wpe   = (const float*)d_in[2];
    const float* ln1w  = (const float*)d_in[3];
    const float* ln1b  = (const float*)d_in[4];
    const float* wqkv  = (const float*)d_in[5];
    const float* bqkv  = (const float*)d_in[6];
    const float* wao   = (const float*)d_in[7];
    const float* bao   = (const float*)d_in[8];
    const float* ln2w  = (const float*)d_in[9];
    const float* ln2b  = (const float*)d_in[10];
    const float* wfc   = (const float*)d_in[11];
    const float* bfc   = (const float*)d_in[12];
    const float* wfp   = (const float*)d_in[13];
    const float* bfp   = (const float*)d_in[14];
    const float* lnfw  = (const float*)d_in[15];
    const float* lnfb  = (const float*)d_in[16];
    const float* whead = (const float*)d_in[17];

    float* x;
    f16 *qkv16, *hh, *hl, *yh, *yl, *ffh, *ffl;
    f16 *wqkvT, *waoT, *wfcT, *wfpT;
    cudaGetSymbolAddress((void**)&x, g_x);
    cudaGetSymbolAddress((void**)&qkv16, g_qkv16);
    cudaGetSymbolAddress((void**)&hh, g_hh);
    cudaGetSymbolAddress((void**)&hl, g_hl);
    cudaGetSymbolAddress((void**)&yh, g_yh);
    cudaGetSymbolAddress((void**)&yl, g_yl);
    cudaGetSymbolAddress((void**)&ffh, g_ffh);
    cudaGetSymbolAddress((void**)&ffl, g_ffl);
    cudaGetSymbolAddress((void**)&wqkvT, g_wqkvT);
    cudaGetSymbolAddress((void**)&waoT, g_waoT);
    cudaGetSymbolAddress((void**)&wfcT, g_wfcT);
    cudaGetSymbolAddress((void**)&wfpT, g_wfpT);

    cudaFuncSetAttribute((const void*)attn16_kernel,
                         cudaFuncAttributeMaxDynamicSharedMemorySize, ATTN_SMEM);
    cudaFuncSetAttribute((const void*)gemm_mma<false, false, 1>,
                         cudaFuncAttributeMaxDynamicSharedMemorySize, GSM3);
    cudaFuncSetAttribute((const void*)gemm_mma<false, true, 0>,
                         cudaFuncAttributeMaxDynamicSharedMemorySize, GSM3);
    cudaFuncSetAttribute((const void*)gemm_mma<true, false, 2>,
                         cudaFuncAttributeMaxDynamicSharedMemorySize, GSM3);

    wsplit_kernel<<<dim3(3 * Cc / 32, Cc / 32, Ll), 256>>>(wqkv, wqkvT, Cc, 3 * Cc);
    wsplit_kernel<<<dim3(Cc / 32, Cc / 32, Ll), 256>>>(wao, waoT, Cc, Cc);
    wsplit_kernel<<<dim3(4 * Cc / 32, Cc / 32, Ll), 256>>>(wfc, wfcT, Cc, 4 * Cc);
    wsplit_kernel<<<dim3(Cc / 32, 4 * Cc / 32, Ll), 256>>>(wfp, wfpT, 4 * Cc, Cc);

    embed_kernel<<<BT, 192>>>(idx, wte, wpe, x);

    for (int l = 0; l < Ll; l++) {
        ln_kernel<<<BT, 256>>>(x, ln1w + l * Cc, ln1b + l * Cc, hh, hl);
        gemm_mma<false, false, 1><<<dim3(18, 32), 256, GSM3>>>(
            hh, hl, wqkvT + (size_t)l * 3 * Cc * Cc, bqkv + l * 3 * Cc,
            nullptr, nullptr, qkv16, nullptr, BT, 3 * Cc, Cc);
        attn16_kernel<<<dim3(Tt / 128, Bq * Hh), 256, ATTN_SMEM>>>(qkv16, yh, yl);
        gemm_mma<false, true, 0><<<dim3(6, 32), 256, GSM3>>>(
            yh, yl, waoT + (size_t)l * Cc * Cc, bao + l * Cc,
            x, x, nullptr, nullptr, BT, Cc, Cc);
        ln_kernel<<<BT, 256>>>(x, ln2w + l * Cc, ln2b + l * Cc, hh, hl);
        gemm_mma<true, false, 2><<<dim3(24, 32), 256, GSM3>>>(
            hh, hl, wfcT + (size_t)l * 4 * Cc * Cc, bfc + l * 4 * Cc,
            nullptr, nullptr, ffh, ffl, BT, 4 * Cc, Cc);
        gemm_mma<false, true, 0><<<dim3(6, 32), 256, GSM3>>>(
            ffh, ffl, wfpT + (size_t)l * Cc * 4 * Cc, bfp + l * Cc,
            x, x, nullptr, nullptr, BT, Cc, 4 * Cc);
    }

    head_kernel<<<BT, 256>>>(x, lnfw, lnfb, whead, (float*)d_out);
}